// round 1
// baseline (speedup 1.0000x reference)
#include <cuda_runtime.h>
#include <stdint.h>

#define NB 1024

// ---------------- scratch (no allocations allowed) ----------------
__device__ float g_maxabs[4];                        // w1, w2, wl1, wl2 max|.|
__device__ __align__(16) int8_t g_qx  [NB * 784];    // quantized input q
__device__ __align__(16) int8_t g_qw1 [32 * 9];      // [oc][kpos]
__device__ __align__(16) int8_t g_qw2 [64 * 9 * 32]; // [oc][kpos][ic]
__device__ __align__(16) int8_t g_act1[NB * 169 * 32];  // [b][pix][ch]
__device__ __align__(16) int8_t g_act2[NB * 1600];      // fc1 input (b, oc*25+p)
__device__ __align__(16) int8_t g_qwl1[4096 * 1600];    // [n][k]
__device__ __align__(16) int8_t g_act3[NB * 4096];      // fc1 output q (0..15)
__device__ __align__(16) int8_t g_qwl2[10 * 4096];      // [n][k]

__device__ __forceinline__ int clampi(int v, int lo, int hi) {
    return max(lo, min(hi, v));
}

// ---------------- scale setup ----------------
__global__ void reset_k() {
    if (threadIdx.x < 4) g_maxabs[threadIdx.x] = 0.0f;
}

__global__ void maxabs_k(const float* __restrict__ w, int n, int idx) {
    float m = 0.0f;
    for (int i = blockIdx.x * blockDim.x + threadIdx.x; i < n;
         i += gridDim.x * blockDim.x)
        m = fmaxf(m, fabsf(w[i]));
    #pragma unroll
    for (int o = 16; o; o >>= 1) m = fmaxf(m, __shfl_xor_sync(0xffffffffu, m, o));
    __shared__ float sm[32];
    int lane = threadIdx.x & 31, wid = threadIdx.x >> 5;
    if (lane == 0) sm[wid] = m;
    __syncthreads();
    if (wid == 0) {
        m = (lane < (int)(blockDim.x >> 5)) ? sm[lane] : 0.0f;
        #pragma unroll
        for (int o = 16; o; o >>= 1) m = fmaxf(m, __shfl_xor_sync(0xffffffffu, m, o));
        if (lane == 0) atomicMax((int*)&g_maxabs[idx], __float_as_int(m));
    }
}

// ---------------- quantization kernels ----------------
__global__ void quant_x_k(const float* __restrict__ x, const float* __restrict__ sp) {
    float s = *sp;
    const int n = NB * 784;
    for (int i = blockIdx.x * blockDim.x + threadIdx.x; i < n;
         i += gridDim.x * blockDim.x) {
        int q = clampi((int)rintf(x[i] / s), -8, 7);
        g_qx[i] = (int8_t)q;
    }
}

__global__ void quant_w1_k(const float* __restrict__ w) {
    float s = g_maxabs[0] / 7.0f;
    int i = blockIdx.x * blockDim.x + threadIdx.x;
    if (i < 32 * 9) {
        int q = clampi((int)rintf(w[i] / s), -7, 7);
        g_qw1[i] = (int8_t)q;
    }
}

__global__ void quant_w2_k(const float* __restrict__ w) {
    float s = g_maxabs[1] / 7.0f;
    int i = blockIdx.x * blockDim.x + threadIdx.x;
    if (i < 64 * 9 * 32) {
        int oc = i / 288, r = i % 288;
        int pos = r >> 5, ic = r & 31;
        float v = w[(oc * 32 + ic) * 9 + pos];
        int q = clampi((int)rintf(v / s), -7, 7);
        g_qw2[i] = (int8_t)q;
    }
}

__global__ void quant_wl1_k(const float* __restrict__ w) {
    float s = g_maxabs[2] / 7.0f;
    const int n = 4096 * 1600;
    for (int i = blockIdx.x * blockDim.x + threadIdx.x; i < n;
         i += gridDim.x * blockDim.x) {
        int q = clampi((int)rintf(w[i] / s), -7, 7);
        g_qwl1[i] = (int8_t)q;
    }
}

__global__ void quant_wl2_k(const float* __restrict__ w) {
    float s = g_maxabs[3] / 7.0f;
    const int n = 10 * 4096;
    for (int i = blockIdx.x * blockDim.x + threadIdx.x; i < n;
         i += gridDim.x * blockDim.x) {
        int q = clampi((int)rintf(w[i] / s), -7, 7);
        g_qwl2[i] = (int8_t)q;
    }
}

// ---------------- conv1 + relu-fq + pool + signed-fq ----------------
__global__ void conv1_k(const float* __restrict__ s_in_p,
                        const float* __restrict__ s_a1_p) {
    __shared__ __align__(16) int8_t sx[784];
    __shared__ __align__(16) int8_t sw[288];
    int b = blockIdx.x, tid = threadIdx.x;
    {
        const int* gx = (const int*)(g_qx + b * 784);
        int* sxi = (int*)sx;
        for (int i = tid; i < 196; i += 256) sxi[i] = gx[i];
        const int* gw = (const int*)g_qw1;
        int* swi = (int*)sw;
        if (tid < 72) swi[tid] = gw[tid];
    }
    __syncthreads();
    float s_in = *s_in_p, s_a1 = *s_a1_p;
    float mul = s_in * (g_maxabs[0] / 7.0f);

    for (int o = tid; o < 32 * 169; o += 256) {
        int oc = o / 169, pix = o % 169;
        int py = pix / 13, px = pix % 13;
        int qm = 0;
        #pragma unroll
        for (int dy = 0; dy < 2; dy++)
            #pragma unroll
            for (int dx = 0; dx < 2; dx++) {
                int cy = 2 * py + dy, cx = 2 * px + dx;
                int acc = 0;
                #pragma unroll
                for (int ky = 0; ky < 3; ky++)
                    #pragma unroll
                    for (int kx = 0; kx < 3; kx++)
                        acc += (int)sx[(cy + ky) * 28 + cx + kx]
                             * (int)sw[oc * 9 + ky * 3 + kx];
                float v = (float)acc * mul;
                int q = clampi((int)rintf(v / s_a1), 0, 15);
                qm = max(qm, q);
            }
        int q2 = clampi((int)rintf((float)qm * s_a1 / s_in), -8, 7);
        g_act1[b * 5408 + pix * 32 + oc] = (int8_t)q2;
    }
}

// ---------------- conv2 + relu-fq + pool + signed-fq ----------------
__global__ void conv2_k(const float* __restrict__ s_in_p,
                        const float* __restrict__ s_a2_p) {
    __shared__ __align__(16) int8_t sa[5408];    // [pix 169][ch 32]
    __shared__ __align__(16) int8_t sw[18432];   // [oc 64][kpos 9][ic 32]
    int b = blockIdx.x, tid = threadIdx.x;
    {
        const int* ga = (const int*)(g_act1 + b * 5408);
        int* sai = (int*)sa;
        for (int i = tid; i < 1352; i += 256) sai[i] = ga[i];
        const int* gw = (const int*)g_qw2;
        int* swi = (int*)sw;
        for (int i = tid; i < 4608; i += 256) swi[i] = gw[i];
    }
    __syncthreads();
    float s_in = *s_in_p, s_a2 = *s_a2_p;
    float mul = s_in * (g_maxabs[1] / 7.0f);

    for (int o = tid; o < 1600; o += 256) {
        int oc = o / 25, p = o % 25;
        int py = p / 5, px = p % 5;
        int qm = 0;
        #pragma unroll
        for (int dy = 0; dy < 2; dy++)
            #pragma unroll
            for (int dx = 0; dx < 2; dx++) {
                int cy = 2 * py + dy, cx = 2 * px + dx;
                int acc = 0;
                #pragma unroll
                for (int ky = 0; ky < 3; ky++) {
                    int row = cy + ky;
                    #pragma unroll
                    for (int kx = 0; kx < 3; kx++) {
                        const int* ap = (const int*)(sa + (row * 13 + cx + kx) * 32);
                        const int* wp = (const int*)(sw + (oc * 9 + ky * 3 + kx) * 32);
                        #pragma unroll
                        for (int t = 0; t < 8; t++)
                            acc = __dp4a(ap[t], wp[t], acc);
                    }
                }
                float v = (float)acc * mul;
                int q = clampi((int)rintf(v / s_a2), 0, 15);
                qm = max(qm, q);
            }
        int q2 = clampi((int)rintf((float)qm * s_a2 / s_in), -8, 7);
        g_act2[b * 1600 + o] = (int8_t)q2;  // o == oc*25 + py*5 + px
    }
}

// ---------------- fc1: [1024,1600] x [4096,1600]^T, int8 dp4a GEMM ----------------
// BM=128, BN=64, BK=64 bytes (16 ints). 256 threads, each 8x4 outputs.
__global__ void fc1_k(const float* __restrict__ s_in_p,
                      const float* __restrict__ s_a3_p) {
    __shared__ int sA[128][17];
    __shared__ int sB[64][17];
    int tid = threadIdx.x;
    int tx = tid & 15, ty = tid >> 4;
    int bn = blockIdx.x, bm = blockIdx.y;
    const int* Ag = (const int*)g_act2;   // 400 ints per row
    const int* Bg = (const int*)g_qwl1;   // 400 ints per row
    int arow = bm * 128, brow = bn * 64;

    int acc[8][4];
    #pragma unroll
    for (int i = 0; i < 8; i++)
        #pragma unroll
        for (int j = 0; j < 4; j++) acc[i][j] = 0;

    for (int kt = 0; kt < 25; kt++) {
        int c = tid & 15, r0 = tid >> 4;
        #pragma unroll
        for (int l = 0; l < 8; l++) {
            int r = r0 + l * 16;
            sA[r][c] = Ag[(arow + r) * 400 + kt * 16 + c];
        }
        #pragma unroll
        for (int l = 0; l < 4; l++) {
            int r = r0 + l * 16;
            sB[r][c] = Bg[(brow + r) * 400 + kt * 16 + c];
        }
        __syncthreads();
        #pragma unroll
        for (int kk = 0; kk < 16; kk++) {
            int a[8], bb[4];
            #pragma unroll
            for (int i = 0; i < 8; i++) a[i] = sA[ty * 8 + i][kk];
            #pragma unroll
            for (int j = 0; j < 4; j++) bb[j] = sB[tx * 4 + j][kk];
            #pragma unroll
            for (int i = 0; i < 8; i++)
                #pragma unroll
                for (int j = 0; j < 4; j++)
                    acc[i][j] = __dp4a(a[i], bb[j], acc[i][j]);
        }
        __syncthreads();
    }

    float s_in = *s_in_p, s_a3 = *s_a3_p;
    float mul = s_in * (g_maxabs[2] / 7.0f);
    #pragma unroll
    for (int i = 0; i < 8; i++) {
        int m = arow + ty * 8 + i;
        #pragma unroll
        for (int j = 0; j < 4; j++) {
            int n = brow + tx * 4 + j;
            float v = (float)acc[i][j] * mul;
            int q = clampi((int)rintf(v / s_a3), 0, 15);
            g_act3[m * 4096 + n] = (int8_t)q;
        }
    }
}

// ---------------- fc2: [1024,4096] x [10,4096]^T -> out ----------------
__global__ void fc2_k(const float* __restrict__ s_a3_p, float* __restrict__ out) {
    int b = blockIdx.x;
    int wj = threadIdx.x >> 5, lane = threadIdx.x & 31;
    const int* ar = (const int*)(g_act3 + b * 4096);
    const int* wr = (const int*)(g_qwl2 + wj * 4096);
    int acc = 0;
    for (int t = lane; t < 1024; t += 32)
        acc = __dp4a(ar[t], wr[t], acc);
    #pragma unroll
    for (int o = 16; o; o >>= 1) acc += __shfl_xor_sync(0xffffffffu, acc, o);
    if (lane == 0)
        out[b * 10 + wj] = (float)acc * (*s_a3_p) * (g_maxabs[3] / 7.0f);
}

// ---------------- launcher ----------------
extern "C" void kernel_launch(void* const* d_in, const int* in_sizes, int n_in,
                              void* d_out, int out_size) {
    const float* x    = (const float*)d_in[0];
    const float* w1   = (const float*)d_in[1];
    const float* w2   = (const float*)d_in[2];
    const float* wl1  = (const float*)d_in[3];
    const float* wl2  = (const float*)d_in[4];
    const float* s_in = (const float*)d_in[5];
    const float* s_a1 = (const float*)d_in[6];
    const float* s_a2 = (const float*)d_in[7];
    const float* s_a3 = (const float*)d_in[8];
    float* out = (float*)d_out;

    reset_k<<<1, 32>>>();
    maxabs_k<<<1,   256>>>(w1, 32 * 9, 0);
    maxabs_k<<<18,  256>>>(w2, 64 * 32 * 9, 1);
    maxabs_k<<<512, 256>>>(wl1, 4096 * 1600, 2);
    maxabs_k<<<40,  256>>>(wl2, 10 * 4096, 3);

    quant_x_k  <<<784,  256>>>(x, s_in);
    quant_w1_k <<<2,    256>>>(w1);
    quant_w2_k <<<72,   256>>>(w2);
    quant_wl1_k<<<2048, 256>>>(wl1);
    quant_wl2_k<<<160,  256>>>(wl2);

    conv1_k<<<1024, 256>>>(s_in, s_a1);
    conv2_k<<<1024, 256>>>(s_in, s_a2);
    fc1_k<<<dim3(64, 8), 256>>>(s_in, s_a3);
    fc2_k<<<1024, 320>>>(s_a3, out);
}

// round 4
// speedup vs baseline: 1.8925x; 1.8925x over previous
#include <cuda_runtime.h>
#include <cuda_bf16.h>
#include <stdint.h>

#define NB 1024

// ---------------- scratch (no allocations allowed) ----------------
__device__ float g_maxabs[4];                           // w1, w2, wl1, wl2 max|.|
__device__ __align__(16) int8_t g_qx  [NB * 784];       // quantized input q
__device__ __align__(16) int8_t g_qw1 [32 * 9];         // [oc][kpos]
__device__ __align__(16) int8_t g_qw2 [64 * 9 * 32];    // [oc][kpos][ic]
__device__ __align__(16) int8_t g_act1[NB * 169 * 32];  // [b][pix][ch]
__device__ __align__(16) __nv_bfloat16 g_act2_bf[NB * 1600];     // fc1 A (bf16 q)
__device__ __align__(16) __nv_bfloat16 g_qwl1_bf[4096 * 1600];   // fc1 B (bf16 q) [n][k]
__device__ __align__(16) int8_t g_act3[NB * 4096];      // fc1 output q (0..15)
__device__ __align__(16) int8_t g_qwl2[10 * 4096];      // [n][k]

__device__ __forceinline__ int clampi(int v, int lo, int hi) {
    return max(lo, min(hi, v));
}

__device__ __forceinline__ uint32_t smem_u32(const void* p) {
    return (uint32_t)__cvta_generic_to_shared(p);
}
__device__ __forceinline__ void ldsm4(uint32_t& r0, uint32_t& r1, uint32_t& r2,
                                      uint32_t& r3, uint32_t a) {
    asm volatile("ldmatrix.sync.aligned.m8n8.x4.shared.b16 {%0,%1,%2,%3}, [%4];\n"
                 : "=r"(r0), "=r"(r1), "=r"(r2), "=r"(r3) : "r"(a));
}
__device__ __forceinline__ void mma16816(float* c, const uint32_t* a, const uint32_t* b) {
    asm volatile(
        "mma.sync.aligned.m16n8k16.row.col.f32.bf16.bf16.f32 "
        "{%0,%1,%2,%3},{%4,%5,%6,%7},{%8,%9},{%0,%1,%2,%3};\n"
        : "+f"(c[0]), "+f"(c[1]), "+f"(c[2]), "+f"(c[3])
        : "r"(a[0]), "r"(a[1]), "r"(a[2]), "r"(a[3]), "r"(b[0]), "r"(b[1]));
}
#define CPA16(dst, src) \
    asm volatile("cp.async.cg.shared.global [%0], [%1], 16;\n" ::"r"(dst), "l"(src))
#define CPC()  asm volatile("cp.async.commit_group;\n")
#define CPW0() asm volatile("cp.async.wait_group 0;\n")

// ---------------- scale setup ----------------
__global__ void reset_k() {
    if (threadIdx.x < 4) g_maxabs[threadIdx.x] = 0.0f;
}

// n must be a multiple of 4 (all our tensors are)
__global__ void maxabs_k(const float* __restrict__ w, int n, int idx) {
    const float4* w4 = (const float4*)w;
    int n4 = n >> 2;
    float m = 0.0f;
    for (int i = blockIdx.x * blockDim.x + threadIdx.x; i < n4;
         i += gridDim.x * blockDim.x) {
        float4 v = w4[i];
        m = fmaxf(m, fmaxf(fmaxf(fabsf(v.x), fabsf(v.y)),
                           fmaxf(fabsf(v.z), fabsf(v.w))));
    }
    #pragma unroll
    for (int o = 16; o; o >>= 1) m = fmaxf(m, __shfl_xor_sync(0xffffffffu, m, o));
    __shared__ float sm[32];
    int lane = threadIdx.x & 31, wid = threadIdx.x >> 5;
    if (lane == 0) sm[wid] = m;
    __syncthreads();
    if (wid == 0) {
        m = (lane < (int)(blockDim.x >> 5)) ? sm[lane] : 0.0f;
        #pragma unroll
        for (int o = 16; o; o >>= 1) m = fmaxf(m, __shfl_xor_sync(0xffffffffu, m, o));
        if (lane == 0) atomicMax((int*)&g_maxabs[idx], __float_as_int(m));
    }
}

// ---------------- quantization kernels ----------------
__global__ void quant_x_k(const float* __restrict__ x, const float* __restrict__ sp) {
    float inv = 1.0f / *sp;  // s_in is a power of two -> exact
    const int n4 = (NB * 784) >> 2;
    const float4* x4 = (const float4*)x;
    char4* q4 = (char4*)g_qx;
    for (int i = blockIdx.x * blockDim.x + threadIdx.x; i < n4;
         i += gridDim.x * blockDim.x) {
        float4 v = x4[i];
        char4 q;
        q.x = (char)clampi((int)rintf(v.x * inv), -8, 7);
        q.y = (char)clampi((int)rintf(v.y * inv), -8, 7);
        q.z = (char)clampi((int)rintf(v.z * inv), -8, 7);
        q.w = (char)clampi((int)rintf(v.w * inv), -8, 7);
        q4[i] = q;
    }
}

__global__ void quant_w1_k(const float* __restrict__ w) {
    float s = g_maxabs[0] / 7.0f;
    int i = blockIdx.x * blockDim.x + threadIdx.x;
    if (i < 32 * 9) {
        int q = clampi((int)rintf(w[i] / s), -7, 7);
        g_qw1[i] = (int8_t)q;
    }
}

__global__ void quant_w2_k(const float* __restrict__ w) {
    float s = g_maxabs[1] / 7.0f;
    int i = blockIdx.x * blockDim.x + threadIdx.x;
    if (i < 64 * 9 * 32) {
        int oc = i / 288, r = i % 288;
        int pos = r >> 5, ic = r & 31;
        float v = w[(oc * 32 + ic) * 9 + pos];
        int q = clampi((int)rintf(v / s), -7, 7);
        g_qw2[i] = (int8_t)q;
    }
}

__global__ void quant_wl1_k(const float* __restrict__ w) {
    float s = g_maxabs[2] / 7.0f;
    float inv = 1.0f / s;
    const int n4 = (4096 * 1600) >> 2;
    const float4* w4 = (const float4*)w;
    uint2* o4 = (uint2*)g_qwl1_bf;  // 4 bf16 = 8 bytes
    for (int i = blockIdx.x * blockDim.x + threadIdx.x; i < n4;
         i += gridDim.x * blockDim.x) {
        float4 v = w4[i];
        float q0 = (float)clampi((int)rintf(v.x * inv), -7, 7);
        float q1 = (float)clampi((int)rintf(v.y * inv), -7, 7);
        float q2 = (float)clampi((int)rintf(v.z * inv), -7, 7);
        float q3 = (float)clampi((int)rintf(v.w * inv), -7, 7);
        __nv_bfloat162 p0 = __floats2bfloat162_rn(q0, q1);
        __nv_bfloat162 p1 = __floats2bfloat162_rn(q2, q3);
        uint2 out;
        out.x = *(uint32_t*)&p0;
        out.y = *(uint32_t*)&p1;
        o4[i] = out;
    }
}

__global__ void quant_wl2_k(const float* __restrict__ w) {
    float s = g_maxabs[3] / 7.0f;
    const int n = 10 * 4096;
    for (int i = blockIdx.x * blockDim.x + threadIdx.x; i < n;
         i += gridDim.x * blockDim.x) {
        int q = clampi((int)rintf(w[i] / s), -7, 7);
        g_qwl2[i] = (int8_t)q;
    }
}

// ---------------- conv1 + relu-fq + pool + signed-fq ----------------
__global__ void conv1_k(const float* __restrict__ s_in_p,
                        const float* __restrict__ s_a1_p) {
    __shared__ __align__(16) int8_t sx[784];
    __shared__ __align__(16) int8_t sw[288];
    int b = blockIdx.x, tid = threadIdx.x;
    {
        const int* gx = (const int*)(g_qx + b * 784);
        int* sxi = (int*)sx;
        for (int i = tid; i < 196; i += 256) sxi[i] = gx[i];
        const int* gw = (const int*)g_qw1;
        int* swi = (int*)sw;
        if (tid < 72) swi[tid] = gw[tid];
    }
    __syncthreads();
    float s_in = *s_in_p, s_a1 = *s_a1_p;
    float mul = s_in * (g_maxabs[0] / 7.0f);

    for (int o = tid; o < 32 * 169; o += 256) {
        int oc = o / 169, pix = o % 169;
        int py = pix / 13, px = pix % 13;
        int qm = 0;
        #pragma unroll
        for (int dy = 0; dy < 2; dy++)
            #pragma unroll
            for (int dx = 0; dx < 2; dx++) {
                int cy = 2 * py + dy, cx = 2 * px + dx;
                int acc = 0;
                #pragma unroll
                for (int ky = 0; ky < 3; ky++)
                    #pragma unroll
                    for (int kx = 0; kx < 3; kx++)
                        acc += (int)sx[(cy + ky) * 28 + cx + kx]
                             * (int)sw[oc * 9 + ky * 3 + kx];
                float v = (float)acc * mul;
                int q = clampi((int)rintf(v / s_a1), 0, 15);
                qm = max(qm, q);
            }
        int q2 = clampi((int)rintf((float)qm * s_a1 / s_in), -8, 7);
        g_act1[b * 5408 + pix * 32 + oc] = (int8_t)q2;
    }
}

// ---------------- conv2 + relu-fq + pool + signed-fq (weights hoisted) ----------------
__global__ void conv2_k(const float* __restrict__ s_in_p,
                        const float* __restrict__ s_a2_p) {
    __shared__ __align__(16) int8_t sa[5408];    // [pix 169][ch 32]
    __shared__ __align__(16) int8_t sw[18432];   // [oc 64][kpos 9][ic 32]
    int b = blockIdx.x, tid = threadIdx.x;
    {
        const int* ga = (const int*)(g_act1 + b * 5408);
        int* sai = (int*)sa;
        for (int i = tid; i < 1352; i += 256) sai[i] = ga[i];
        const int* gw = (const int*)g_qw2;
        int* swi = (int*)sw;
        for (int i = tid; i < 4608; i += 256) swi[i] = gw[i];
    }
    __syncthreads();
    float s_in = *s_in_p, s_a2 = *s_a2_p;
    float mul = s_in * (g_maxabs[1] / 7.0f);

    for (int o = tid; o < 1600; o += 256) {
        int oc = o / 25, p = o % 25;
        int py = p / 5, px = p % 5;
        int acc[4] = {0, 0, 0, 0};
        #pragma unroll
        for (int ky = 0; ky < 3; ky++)
            #pragma unroll
            for (int kx = 0; kx < 3; kx++) {
                const int* wp = (const int*)(sw + (oc * 9 + ky * 3 + kx) * 32);
                int w[8];
                #pragma unroll
                for (int t = 0; t < 8; t++) w[t] = wp[t];
                #pragma unroll
                for (int dy = 0; dy < 2; dy++)
                    #pragma unroll
                    for (int dx = 0; dx < 2; dx++) {
                        int row = (2 * py + dy + ky) * 13 + 2 * px + dx + kx;
                        const int* ap = (const int*)(sa + row * 32);
                        int* a = &acc[dy * 2 + dx];
                        #pragma unroll
                        for (int t = 0; t < 8; t++) *a = __dp4a(ap[t], w[t], *a);
                    }
            }
        int qm = 0;
        #pragma unroll
        for (int q4 = 0; q4 < 4; q4++) {
            float v = (float)acc[q4] * mul;
            int q = clampi((int)rintf(v / s_a2), 0, 15);
            qm = max(qm, q);
        }
        int q2 = clampi((int)rintf((float)qm * s_a2 / s_in), -8, 7);
        g_act2_bf[b * 1600 + o] = __float2bfloat16((float)q2);
    }
}

// ---------------- fc1: bf16 tensor-core GEMM [1024,1600] x [4096,1600]^T ----------------
// BM=128, BN=128, BK=32, 256 threads (8 warps = 2m x 4n), warp tile 64x32.
__global__ __launch_bounds__(256) void fc1_mma_k(const float* __restrict__ s_in_p,
                                                 const float* __restrict__ s_a3_p) {
    __shared__ __align__(16) __nv_bfloat16 sA[2][128 * 40];  // 80B row stride
    __shared__ __align__(16) __nv_bfloat16 sB[2][128 * 40];
    const int BUFB = 128 * 40 * 2;  // bytes per buffer

    int tid = threadIdx.x, lane = tid & 31, wid = tid >> 5;
    int wm = wid >> 2, wn = wid & 3;
    int bm = blockIdx.y, bn = blockIdx.x;

    int lrow = tid >> 2, lseg = tid & 3;  // loader: 64 rows x 4 x 16B, two halves
    const char* gA0 = (const char*)g_act2_bf + (size_t)bm * 128 * 3200
                      + (size_t)lrow * 3200 + lseg * 16;
    const char* gB0 = (const char*)g_qwl1_bf + (size_t)bn * 128 * 3200
                      + (size_t)lrow * 3200 + lseg * 16;
    uint32_t smA0 = smem_u32(&sA[0][0]) + lrow * 80 + lseg * 16;
    uint32_t smB0 = smem_u32(&sB[0][0]) + lrow * 80 + lseg * 16;

    float c[4][4][4];
    #pragma unroll
    for (int i = 0; i < 4; i++)
        #pragma unroll
        for (int j = 0; j < 4; j++)
            #pragma unroll
            for (int e = 0; e < 4; e++) c[i][j][e] = 0.0f;

    // preload kt=0
    CPA16(smA0, gA0);
    CPA16(smA0 + 64 * 80, gA0 + 64 * 3200);
    CPA16(smB0, gB0);
    CPA16(smB0 + 64 * 80, gB0 + 64 * 3200);
    CPC();
    CPW0();
    __syncthreads();

    uint32_t saL = smem_u32(&sA[0][0]) + (wm * 64 + (lane & 15)) * 80 + (lane >> 4) * 16;
    uint32_t sbL = smem_u32(&sB[0][0])
                 + (wn * 32 + ((lane >> 4) << 3) + (lane & 7)) * 80
                 + ((lane >> 3) & 1) * 16;

    int buf = 0;
    for (int kt = 0; kt < 50; kt++) {
        if (kt < 49) {
            int nb = buf ^ 1;
            const char* ga = gA0 + (kt + 1) * 64;
            const char* gb = gB0 + (kt + 1) * 64;
            uint32_t da = smA0 + nb * BUFB, db = smB0 + nb * BUFB;
            CPA16(da, ga);
            CPA16(da + 64 * 80, ga + 64 * 3200);
            CPA16(db, gb);
            CPA16(db + 64 * 80, gb + 64 * 3200);
            CPC();
        }
        uint32_t sa = saL + buf * BUFB;
        uint32_t sb = sbL + buf * BUFB;
        #pragma unroll
        for (int ks = 0; ks < 2; ks++) {
            uint32_t a[4][4], b[4][2];
            #pragma unroll
            for (int mt = 0; mt < 4; mt++)
                ldsm4(a[mt][0], a[mt][1], a[mt][2], a[mt][3],
                      sa + mt * 1280 + ks * 32);
            #pragma unroll
            for (int j = 0; j < 2; j++) {
                uint32_t r0, r1, r2, r3;
                ldsm4(r0, r1, r2, r3, sb + j * 1280 + ks * 32);
                b[2 * j][0] = r0; b[2 * j][1] = r1;
                b[2 * j + 1][0] = r2; b[2 * j + 1][1] = r3;
            }
            #pragma unroll
            for (int mt = 0; mt < 4; mt++)
                #pragma unroll
                for (int nt = 0; nt < 4; nt++)
                    mma16816(c[mt][nt], a[mt], b[nt]);
        }
        if (kt < 49) {
            CPW0();
            __syncthreads();
            buf ^= 1;
        }
    }

    float s_in = *s_in_p, s_a3 = *s_a3_p;
    float mul = s_in * (g_maxabs[2] / 7.0f);
    float isa3 = 1.0f / s_a3;  // power of two -> exact
    int r0 = bm * 128 + wm * 64 + (lane >> 2);
    int c0 = bn * 128 + wn * 32 + ((lane & 3) << 1);
    #pragma unroll
    for (int mt = 0; mt < 4; mt++) {
        #pragma unroll
        for (int nt = 0; nt < 4; nt++) {
            int rr = r0 + mt * 16, cc = c0 + nt * 8;
            float* cf = c[mt][nt];
            uchar2 lo, hi;
            lo.x = (uint8_t)clampi((int)rintf(cf[0] * mul * isa3), 0, 15);
            lo.y = (uint8_t)clampi((int)rintf(cf[1] * mul * isa3), 0, 15);
            hi.x = (uint8_t)clampi((int)rintf(cf[2] * mul * isa3), 0, 15);
            hi.y = (uint8_t)clampi((int)rintf(cf[3] * mul * isa3), 0, 15);
            *(uchar2*)(g_act3 + rr * 4096 + cc) = lo;
            *(uchar2*)(g_act3 + (rr + 8) * 4096 + cc) = hi;
        }
    }
}

// ---------------- fc2: [1024,4096] x [10,4096]^T -> out ----------------
__global__ void fc2_k(const float* __restrict__ s_a3_p, float* __restrict__ out) {
    int b = blockIdx.x;
    int wj = threadIdx.x >> 5, lane = threadIdx.x & 31;
    const int* ar = (const int*)(g_act3 + b * 4096);
    const int* wr = (const int*)(g_qwl2 + wj * 4096);
    int acc = 0;
    for (int t = lane; t < 1024; t += 32)
        acc = __dp4a(ar[t], wr[t], acc);
    #pragma unroll
    for (int o = 16; o; o >>= 1) acc += __shfl_xor_sync(0xffffffffu, acc, o);
    if (lane == 0)
        out[b * 10 + wj] = (float)acc * (*s_a3_p) * (g_maxabs[3] / 7.0f);
}

// ---------------- launcher ----------------
extern "C" void kernel_launch(void* const* d_in, const int* in_sizes, int n_in,
                              void* d_out, int out_size) {
    const float* x    = (const float*)d_in[0];
    const float* w1   = (const float*)d_in[1];
    const float* w2   = (const float*)d_in[2];
    const float* wl1  = (const float*)d_in[3];
    const float* wl2  = (const float*)d_in[4];
    const float* s_in = (const float*)d_in[5];
    const float* s_a1 = (const float*)d_in[6];
    const float* s_a2 = (const float*)d_in[7];
    const float* s_a3 = (const float*)d_in[8];
    float* out = (float*)d_out;

    reset_k<<<1, 32>>>();
    maxabs_k<<<1,    256>>>(w1, 32 * 9 * 4 / 4, 0);        // 288
    maxabs_k<<<18,   256>>>(w2, 64 * 32 * 9, 1);
    maxabs_k<<<1024, 256>>>(wl1, 4096 * 1600, 2);
    maxabs_k<<<40,   256>>>(wl2, 10 * 4096, 3);

    quant_x_k  <<<392,  256>>>(x, s_in);
    quant_w1_k <<<2,    256>>>(w1);
    quant_w2_k <<<72,   256>>>(w2);
    quant_wl1_k<<<2048, 256>>>(wl1);
    quant_wl2_k<<<160,  256>>>(wl2);

    conv1_k<<<1024, 256>>>(s_in, s_a1);
    conv2_k<<<1024, 256>>>(s_in, s_a2);
    fc1_mma_k<<<dim3(32, 8), 256>>>(s_in, s_a3);
    fc2_k<<<1024, 320>>>(s_a3, out);
}

// round 5
// speedup vs baseline: 1.9869x; 1.0499x over previous
#include <cuda_runtime.h>
#include <cuda_bf16.h>
#include <stdint.h>

#define NB 1024

// ---------------- scratch (no allocations allowed) ----------------
__device__ float g_maxabs[4];                           // w1, w2, wl1, wl2 max|.|
__device__ __align__(16) int8_t g_qx  [NB * 784];       // quantized input q
__device__ __align__(16) int8_t g_qw1 [32 * 9];         // [oc][kpos]
__device__ __align__(16) int8_t g_qw2 [64 * 9 * 32];    // [oc][kpos 9][ic 32] rows of 288
__device__ __align__(16) int8_t g_act1[NB * 169 * 32];  // [b][pix][ch]
__device__ __align__(16) int8_t g_act2[NB * 1600];      // fc1 A (s8 q) [b][oc*25+p]
__device__ __align__(16) int8_t g_qwl1[4096 * 1600];    // fc1 B (s8 q) [n][k]
__device__ __align__(16) int8_t g_act3[NB * 4096];      // fc1 output q (0..15)
__device__ __align__(16) int8_t g_qwl2[10 * 4096];      // [n][k]

__device__ __forceinline__ int clampi(int v, int lo, int hi) {
    return max(lo, min(hi, v));
}
__device__ __forceinline__ uint32_t smem_u32(const void* p) {
    return (uint32_t)__cvta_generic_to_shared(p);
}
__device__ __forceinline__ void ldsm4(uint32_t& r0, uint32_t& r1, uint32_t& r2,
                                      uint32_t& r3, uint32_t a) {
    asm volatile("ldmatrix.sync.aligned.m8n8.x4.shared.b16 {%0,%1,%2,%3}, [%4];\n"
                 : "=r"(r0), "=r"(r1), "=r"(r2), "=r"(r3) : "r"(a));
}
__device__ __forceinline__ void imma16832(int* c, const uint32_t* a, const uint32_t* b) {
    asm volatile(
        "mma.sync.aligned.m16n8k32.row.col.s32.s8.s8.s32 "
        "{%0,%1,%2,%3},{%4,%5,%6,%7},{%8,%9},{%0,%1,%2,%3};\n"
        : "+r"(c[0]), "+r"(c[1]), "+r"(c[2]), "+r"(c[3])
        : "r"(a[0]), "r"(a[1]), "r"(a[2]), "r"(a[3]), "r"(b[0]), "r"(b[1]));
}
#define CPA16(dst, src) \
    asm volatile("cp.async.cg.shared.global [%0], [%1], 16;\n" ::"r"(dst), "l"(src))
#define CPC()  asm volatile("cp.async.commit_group;\n")
#define CPW0() asm volatile("cp.async.wait_group 0;\n")

// ---------------- scale setup ----------------
__global__ void reset_k() {
    if (threadIdx.x < 4) g_maxabs[threadIdx.x] = 0.0f;
}

// n multiple of 4; 4-way ILP
__global__ void maxabs_k(const float* __restrict__ w, int n, int idx) {
    const float4* w4 = (const float4*)w;
    int n4 = n >> 2;
    int G = gridDim.x * blockDim.x;
    int i0 = blockIdx.x * blockDim.x + threadIdx.x;
    float m0 = 0.f, m1 = 0.f, m2 = 0.f, m3 = 0.f;
    for (int i = i0; i < n4; i += 4 * G) {
        float4 v = w4[i];
        m0 = fmaxf(m0, fmaxf(fmaxf(fabsf(v.x), fabsf(v.y)),
                             fmaxf(fabsf(v.z), fabsf(v.w))));
        int i1 = i + G;
        if (i1 < n4) {
            float4 u = w4[i1];
            m1 = fmaxf(m1, fmaxf(fmaxf(fabsf(u.x), fabsf(u.y)),
                                 fmaxf(fabsf(u.z), fabsf(u.w))));
        }
        int i2 = i + 2 * G;
        if (i2 < n4) {
            float4 u = w4[i2];
            m2 = fmaxf(m2, fmaxf(fmaxf(fabsf(u.x), fabsf(u.y)),
                                 fmaxf(fabsf(u.z), fabsf(u.w))));
        }
        int i3 = i + 3 * G;
        if (i3 < n4) {
            float4 u = w4[i3];
            m3 = fmaxf(m3, fmaxf(fmaxf(fabsf(u.x), fabsf(u.y)),
                                 fmaxf(fabsf(u.z), fabsf(u.w))));
        }
    }
    float m = fmaxf(fmaxf(m0, m1), fmaxf(m2, m3));
    #pragma unroll
    for (int o = 16; o; o >>= 1) m = fmaxf(m, __shfl_xor_sync(0xffffffffu, m, o));
    __shared__ float sm[32];
    int lane = threadIdx.x & 31, wid = threadIdx.x >> 5;
    if (lane == 0) sm[wid] = m;
    __syncthreads();
    if (wid == 0) {
        m = (lane < (int)(blockDim.x >> 5)) ? sm[lane] : 0.0f;
        #pragma unroll
        for (int o = 16; o; o >>= 1) m = fmaxf(m, __shfl_xor_sync(0xffffffffu, m, o));
        if (lane == 0) atomicMax((int*)&g_maxabs[idx], __float_as_int(m));
    }
}

// ---------------- quantization ----------------
__global__ void quant_x_k(const float* __restrict__ x, const float* __restrict__ sp) {
    float inv = 1.0f / *sp;  // s_in power of two -> exact
    const int n4 = (NB * 784) >> 2;
    const float4* x4 = (const float4*)x;
    char4* q4 = (char4*)g_qx;
    for (int i = blockIdx.x * blockDim.x + threadIdx.x; i < n4;
         i += gridDim.x * blockDim.x) {
        float4 v = x4[i];
        char4 q;
        q.x = (char)clampi((int)rintf(v.x * inv), -8, 7);
        q.y = (char)clampi((int)rintf(v.y * inv), -8, 7);
        q.z = (char)clampi((int)rintf(v.z * inv), -8, 7);
        q.w = (char)clampi((int)rintf(v.w * inv), -8, 7);
        q4[i] = q;
    }
}

// merged: wl2 (blocks 0..159), w2 (160..231), w1 (232..233)
__global__ void quant_small_k(const float* __restrict__ w1,
                              const float* __restrict__ w2,
                              const float* __restrict__ wl2) {
    int bx = blockIdx.x, tid = threadIdx.x;
    if (bx < 160) {
        float s = g_maxabs[3] / 7.0f;
        int i = bx * 256 + tid;
        if (i < 10 * 4096)
            g_qwl2[i] = (int8_t)clampi((int)rintf(wl2[i] / s), -7, 7);
    } else if (bx < 232) {
        float s = g_maxabs[1] / 7.0f;
        int i = (bx - 160) * 256 + tid;
        if (i < 64 * 9 * 32) {
            int oc = i / 288, r = i % 288;
            int pos = r >> 5, ic = r & 31;
            float v = w2[(oc * 32 + ic) * 9 + pos];
            g_qw2[i] = (int8_t)clampi((int)rintf(v / s), -7, 7);
        }
    } else {
        float s = g_maxabs[0] / 7.0f;
        int i = (bx - 232) * 256 + tid;
        if (i < 32 * 9)
            g_qw1[i] = (int8_t)clampi((int)rintf(w1[i] / s), -7, 7);
    }
}

__global__ void quant_wl1_k(const float* __restrict__ w) {
    float s = g_maxabs[2] / 7.0f;
    float inv = 1.0f / s;
    const int n4 = (4096 * 1600) >> 2;
    const float4* w4 = (const float4*)w;
    char4* o4 = (char4*)g_qwl1;
    for (int i = blockIdx.x * blockDim.x + threadIdx.x; i < n4;
         i += gridDim.x * blockDim.x) {
        float4 v = w4[i];
        char4 q;
        q.x = (char)clampi((int)rintf(v.x * inv), -7, 7);
        q.y = (char)clampi((int)rintf(v.y * inv), -7, 7);
        q.z = (char)clampi((int)rintf(v.z * inv), -7, 7);
        q.w = (char)clampi((int)rintf(v.w * inv), -7, 7);
        o4[i] = q;
    }
}

// ---------------- conv1 + relu-fq + pool + signed-fq ----------------
__global__ void conv1_k(const float* __restrict__ s_in_p,
                        const float* __restrict__ s_a1_p) {
    __shared__ __align__(16) int8_t sx[784];
    __shared__ __align__(16) int8_t sw[288];
    int b = blockIdx.x, tid = threadIdx.x;
    {
        const int* gx = (const int*)(g_qx + b * 784);
        int* sxi = (int*)sx;
        for (int i = tid; i < 196; i += 256) sxi[i] = gx[i];
        const int* gw = (const int*)g_qw1;
        int* swi = (int*)sw;
        if (tid < 72) swi[tid] = gw[tid];
    }
    __syncthreads();
    float s_in = *s_in_p, s_a1 = *s_a1_p;
    float mul = s_in * (g_maxabs[0] / 7.0f);

    for (int o = tid; o < 32 * 169; o += 256) {
        int oc = o / 169, pix = o % 169;
        int py = pix / 13, px = pix % 13;
        int qm = 0;
        #pragma unroll
        for (int dy = 0; dy < 2; dy++)
            #pragma unroll
            for (int dx = 0; dx < 2; dx++) {
                int cy = 2 * py + dy, cx = 2 * px + dx;
                int acc = 0;
                #pragma unroll
                for (int ky = 0; ky < 3; ky++)
                    #pragma unroll
                    for (int kx = 0; kx < 3; kx++)
                        acc += (int)sx[(cy + ky) * 28 + cx + kx]
                             * (int)sw[oc * 9 + ky * 3 + kx];
                float v = (float)acc * mul;
                int q = clampi((int)rintf(v / s_a1), 0, 15);
                qm = max(qm, q);
            }
        int q2 = clampi((int)rintf((float)qm * s_a1 / s_in), -8, 7);
        g_act1[b * 5408 + pix * 32 + oc] = (int8_t)q2;
    }
}

// ---------------- conv2 as int8 implicit GEMM + relu-fq + pool + signed-fq ----------
// Per image: A = im2col [128 conv-pix][288], B = w2 [64 oc][288], IMMA m16n8k32.
// Two 64-row halves (C kept in regs), then C dumped to smem, pool 2x2 + fq.
#define IMS 304   // padded row stride (conflict-free ldmatrix: 304/16 mod 8 cycles all)
__global__ __launch_bounds__(256) void conv2_imma_k(const float* __restrict__ s_in_p,
                                                    const float* __restrict__ s_a2_p) {
    __shared__ __align__(16) int8_t smb[2 * 64 * IMS];  // im | sw; later C[128][68] int
    int8_t* im = smb;
    int8_t* sw = smb + 64 * IMS;
    int b = blockIdx.x, tid = threadIdx.x;
    int lane = tid & 31, wid = tid >> 5;
    int wm = wid >> 1, wn = wid & 1;   // wm: m16 tile (of 4), wn: n32 half

    // weights -> smem (rows 288B padded to 304), 64*18 = 1152 x 16B
    for (int idx = tid; idx < 1152; idx += 256) {
        int row = idx / 18, seg = idx % 18;
        CPA16(smem_u32(sw + row * IMS + seg * 16),
              (const char*)g_qw2 + row * 288 + seg * 16);
    }

    int c[2][4][4];
    #pragma unroll
    for (int h = 0; h < 2; h++)
        #pragma unroll
        for (int nt = 0; nt < 4; nt++)
            #pragma unroll
            for (int e = 0; e < 4; e++) c[h][nt][e] = 0;

    uint32_t abase = smem_u32(im) + (wm * 16 + (lane & 15)) * IMS + ((lane >> 4) << 4);
    uint32_t bbase = smem_u32(sw)
                   + (wn * 32 + (lane & 7) + ((lane >> 4) << 3)) * IMS
                   + (((lane >> 3) & 1) << 4);

    for (int h = 0; h < 2; h++) {
        // im2col build: rows p = h*64 .. (h?120:63); each (p,ky): 96B contiguous
        int ntask = (h == 0) ? 1152 : 1026;  // 64*18 / 57*18
        for (int idx = tid; idx < ntask; idx += 256) {
            int pp = idx / 18, r = idx % 18;
            int ky = r / 6, seg = r % 6;
            int p = h * 64 + pp;
            int cy = p / 11, cx = p % 11;
            CPA16(smem_u32(im + pp * IMS + ky * 96 + seg * 16),
                  (const char*)g_act1 + b * 5408
                      + ((cy + ky) * 13 + cx) * 32 + seg * 16);
        }
        CPC(); CPW0();
        __syncthreads();

        #pragma unroll
        for (int ks = 0; ks < 9; ks++) {
            uint32_t a[4];
            ldsm4(a[0], a[1], a[2], a[3], abase + ks * 32);
            uint32_t bb[4][2];
            #pragma unroll
            for (int j = 0; j < 2; j++) {
                uint32_t r0, r1, r2, r3;
                ldsm4(r0, r1, r2, r3, bbase + j * 16 * IMS + ks * 32);
                bb[2 * j][0] = r0;     bb[2 * j][1] = r1;
                bb[2 * j + 1][0] = r2; bb[2 * j + 1][1] = r3;
            }
            #pragma unroll
            for (int nt = 0; nt < 4; nt++)
                imma16832(c[h][nt], a, bb[nt]);
        }
        __syncthreads();  // all reads of im done before rebuild / C dump
    }

    // dump C [128 pix][64 oc] int32, stride 68
    int* Cs = (int*)smb;
    #pragma unroll
    for (int h = 0; h < 2; h++) {
        int row = h * 64 + wm * 16 + (lane >> 2);
        #pragma unroll
        for (int nt = 0; nt < 4; nt++) {
            int col = wn * 32 + nt * 8 + ((lane & 3) << 1);
            int2 v0 = make_int2(c[h][nt][0], c[h][nt][1]);
            int2 v1 = make_int2(c[h][nt][2], c[h][nt][3]);
            *(int2*)(Cs + row * 68 + col) = v0;
            *(int2*)(Cs + (row + 8) * 68 + col) = v1;
        }
    }
    __syncthreads();

    float s_in = *s_in_p, s_a2 = *s_a2_p;
    float mul = s_in * (g_maxabs[1] / 7.0f);
    for (int o = tid; o < 1600; o += 256) {
        int oc = o / 25, p = o % 25;
        int py = p / 5, px = p % 5;
        int qm = 0;
        #pragma unroll
        for (int dy = 0; dy < 2; dy++)
            #pragma unroll
            for (int dx = 0; dx < 2; dx++) {
                int cp = (2 * py + dy) * 11 + 2 * px + dx;
                int acc = Cs[cp * 68 + oc];
                float v = (float)acc * mul;
                int q = clampi((int)rintf(v / s_a2), 0, 15);
                qm = max(qm, q);
            }
        int q2 = clampi((int)rintf((float)qm * s_a2 / s_in), -8, 7);
        g_act2[b * 1600 + o] = (int8_t)q2;
    }
}

// ---------------- fc1: s8 IMMA GEMM [1024,1600] x [4096,1600]^T ----------------
// BM=128, BN=128, BK=64 bytes, 256 threads (8 warps = 2m x 4n), warp tile 64x32.
__global__ __launch_bounds__(256) void fc1_imma_k(const float* __restrict__ s_in_p,
                                                  const float* __restrict__ s_a3_p) {
    __shared__ __align__(16) int8_t sA[2][128 * 80];  // 80B row stride (64 data + pad)
    __shared__ __align__(16) int8_t sB[2][128 * 80];
    const int BUFB = 128 * 80;

    int tid = threadIdx.x, lane = tid & 31, wid = tid >> 5;
    int wm = wid >> 2, wn = wid & 3;
    int bm = blockIdx.y, bn = blockIdx.x;

    int lrow = tid >> 2, lseg = tid & 3;  // 64 rows x 4 segs x 16B; two row-halves
    const char* gA0 = (const char*)g_act2 + (size_t)(bm * 128 + lrow) * 1600 + lseg * 16;
    const char* gB0 = (const char*)g_qwl1 + (size_t)(bn * 128 + lrow) * 1600 + lseg * 16;
    uint32_t smA0 = smem_u32(&sA[0][0]) + lrow * 80 + lseg * 16;
    uint32_t smB0 = smem_u32(&sB[0][0]) + lrow * 80 + lseg * 16;

    int c[4][4][4];
    #pragma unroll
    for (int i = 0; i < 4; i++)
        #pragma unroll
        for (int j = 0; j < 4; j++)
            #pragma unroll
            for (int e = 0; e < 4; e++) c[i][j][e] = 0;

    CPA16(smA0, gA0);
    CPA16(smA0 + 64 * 80, gA0 + (size_t)64 * 1600);
    CPA16(smB0, gB0);
    CPA16(smB0 + 64 * 80, gB0 + (size_t)64 * 1600);
    CPC(); CPW0();
    __syncthreads();

    uint32_t saL = smem_u32(&sA[0][0]) + (wm * 64 + (lane & 15)) * 80 + ((lane >> 4) << 4);
    uint32_t sbL = smem_u32(&sB[0][0])
                 + (wn * 32 + (lane & 7) + ((lane >> 4) << 3)) * 80
                 + (((lane >> 3) & 1) << 4);

    int buf = 0;
    for (int kt = 0; kt < 25; kt++) {
        if (kt < 24) {
            int nb = buf ^ 1;
            const char* ga = gA0 + (kt + 1) * 64;
            const char* gb = gB0 + (kt + 1) * 64;
            uint32_t da = smA0 + nb * BUFB, db = smB0 + nb * BUFB;
            CPA16(da, ga);
            CPA16(da + 64 * 80, ga + (size_t)64 * 1600);
            CPA16(db, gb);
            CPA16(db + 64 * 80, gb + (size_t)64 * 1600);
            CPC();
        }
        uint32_t sa = saL + buf * BUFB;
        uint32_t sb = sbL + buf * BUFB;
        #pragma unroll
        for (int ks = 0; ks < 2; ks++) {
            uint32_t a[4][4], bb[4][2];
            #pragma unroll
            for (int mt = 0; mt < 4; mt++)
                ldsm4(a[mt][0], a[mt][1], a[mt][2], a[mt][3],
                      sa + mt * 16 * 80 + ks * 32);
            #pragma unroll
            for (int j = 0; j < 2; j++) {
                uint32_t r0, r1, r2, r3;
                ldsm4(r0, r1, r2, r3, sb + j * 16 * 80 + ks * 32);
                bb[2 * j][0] = r0;     bb[2 * j][1] = r1;
                bb[2 * j + 1][0] = r2; bb[2 * j + 1][1] = r3;
            }
            #pragma unroll
            for (int mt = 0; mt < 4; mt++)
                #pragma unroll
                for (int nt = 0; nt < 4; nt++)
                    imma16832(c[mt][nt], a[mt], bb[nt]);
        }
        if (kt < 24) {
            CPW0();
            __syncthreads();
            buf ^= 1;
        }
    }

    float s_in = *s_in_p, s_a3 = *s_a3_p;
    float mul = s_in * (g_maxabs[2] / 7.0f);
    float isa3 = 1.0f / s_a3;  // power of two -> exact
    int r0 = bm * 128 + wm * 64 + (lane >> 2);
    int c0 = bn * 128 + wn * 32 + ((lane & 3) << 1);
    #pragma unroll
    for (int mt = 0; mt < 4; mt++) {
        #pragma unroll
        for (int nt = 0; nt < 4; nt++) {
            int rr = r0 + mt * 16, cc = c0 + nt * 8;
            int* cf = c[mt][nt];
            uchar2 lo, hi;
            lo.x = (uint8_t)clampi((int)rintf((float)cf[0] * mul * isa3), 0, 15);
            lo.y = (uint8_t)clampi((int)rintf((float)cf[1] * mul * isa3), 0, 15);
            hi.x = (uint8_t)clampi((int)rintf((float)cf[2] * mul * isa3), 0, 15);
            hi.y = (uint8_t)clampi((int)rintf((float)cf[3] * mul * isa3), 0, 15);
            *(uchar2*)(g_act3 + rr * 4096 + cc) = lo;
            *(uchar2*)(g_act3 + (rr + 8) * 4096 + cc) = hi;
        }
    }
}

// ---------------- fc2: [1024,4096] x [10,4096]^T -> out ----------------
__global__ void fc2_k(const float* __restrict__ s_a3_p, float* __restrict__ out) {
    int b = blockIdx.x;
    int wj = threadIdx.x >> 5, lane = threadIdx.x & 31;
    const int* ar = (const int*)(g_act3 + b * 4096);
    const int* wr = (const int*)(g_qwl2 + wj * 4096);
    int acc = 0;
    for (int t = lane; t < 1024; t += 32)
        acc = __dp4a(ar[t], wr[t], acc);
    #pragma unroll
    for (int o = 16; o; o >>= 1) acc += __shfl_xor_sync(0xffffffffu, acc, o);
    if (lane == 0)
        out[b * 10 + wj] = (float)acc * (*s_a3_p) * (g_maxabs[3] / 7.0f);
}

// ---------------- launcher ----------------
extern "C" void kernel_launch(void* const* d_in, const int* in_sizes, int n_in,
                              void* d_out, int out_size) {
    const float* x    = (const float*)d_in[0];
    const float* w1   = (const float*)d_in[1];
    const float* w2   = (const float*)d_in[2];
    const float* wl1  = (const float*)d_in[3];
    const float* wl2  = (const float*)d_in[4];
    const float* s_in = (const float*)d_in[5];
    const float* s_a1 = (const float*)d_in[6];
    const float* s_a2 = (const float*)d_in[7];
    const float* s_a3 = (const float*)d_in[8];
    float* out = (float*)d_out;

    reset_k<<<1, 32>>>();
    maxabs_k<<<1,    256>>>(w1, 288, 0);
    maxabs_k<<<18,   256>>>(w2, 64 * 32 * 9, 1);
    maxabs_k<<<1024, 256>>>(wl1, 4096 * 1600, 2);
    maxabs_k<<<40,   256>>>(wl2, 10 * 4096, 3);

    quant_x_k  <<<392,  256>>>(x, s_in);
    quant_small_k<<<234, 256>>>(w1, w2, wl2);
    quant_wl1_k<<<2048, 256>>>(wl1);

    conv1_k<<<1024, 256>>>(s_in, s_a1);
    conv2_imma_k<<<1024, 256>>>(s_in, s_a2);
    fc1_imma_k<<<dim3(32, 8), 256>>>(s_in, s_a3);
    fc2_k<<<1024, 320>>>(s_a3, out);
}

// round 7
// speedup vs baseline: 2.2297x; 1.1222x over previous
#include <cuda_runtime.h>
#include <cuda_bf16.h>
#include <stdint.h>

#define NB 1024

// ---------------- scratch (no allocations allowed) ----------------
__device__ float g_maxabs[4];                           // w1, w2, wl1, wl2 max|.|
__device__ __align__(16) int8_t g_qx  [NB * 784];       // quantized input q
__device__ __align__(16) int8_t g_qw1 [32 * 9];         // [oc][kpos]
__device__ __align__(16) int8_t g_qw2 [64 * 9 * 32];    // [oc][kpos 9][ic 32] rows of 288
__device__ __align__(16) int8_t g_act2[NB * 1600];      // fc1 A (s8 q) [b][oc*25+p]
__device__ __align__(16) int8_t g_qwl1[4096 * 1600];    // fc1 B (s8 q) [n][k]
__device__ __align__(16) int8_t g_act3[NB * 4096];      // fc1 output q (0..15)
__device__ __align__(16) int8_t g_qwl2[10 * 4096];      // [n][k]

__device__ __forceinline__ int clampi(int v, int lo, int hi) {
    return max(lo, min(hi, v));
}
__device__ __forceinline__ uint32_t smem_u32(const void* p) {
    return (uint32_t)__cvta_generic_to_shared(p);
}
__device__ __forceinline__ void ldsm4(uint32_t& r0, uint32_t& r1, uint32_t& r2,
                                      uint32_t& r3, uint32_t a) {
    asm volatile("ldmatrix.sync.aligned.m8n8.x4.shared.b16 {%0,%1,%2,%3}, [%4];\n"
                 : "=r"(r0), "=r"(r1), "=r"(r2), "=r"(r3) : "r"(a));
}
__device__ __forceinline__ void imma16832(int* c, const uint32_t* a, const uint32_t* b) {
    asm volatile(
        "mma.sync.aligned.m16n8k32.row.col.s32.s8.s8.s32 "
        "{%0,%1,%2,%3},{%4,%5,%6,%7},{%8,%9},{%0,%1,%2,%3};\n"
        : "+r"(c[0]), "+r"(c[1]), "+r"(c[2]), "+r"(c[3])
        : "r"(a[0]), "r"(a[1]), "r"(a[2]), "r"(a[3]), "r"(b[0]), "r"(b[1]));
}
#define CPA16(dst, src) \
    asm volatile("cp.async.cg.shared.global [%0], [%1], 16;\n" ::"r"(dst), "l"(src))
#define CPC()  asm volatile("cp.async.commit_group;\n")
#define CPW0() asm volatile("cp.async.wait_group 0;\n")
#define CPW1() asm volatile("cp.async.wait_group 1;\n")

// ---------------- scale setup ----------------
__global__ void reset_k() {
    if (threadIdx.x < 4) g_maxabs[threadIdx.x] = 0.0f;
}

__device__ void maxabs_dev(const float* __restrict__ w, int n4, int idx,
                           int bid, int nblocks) {
    const float4* w4 = (const float4*)w;
    int G = nblocks * 256;
    int i0 = bid * 256 + threadIdx.x;
    float m0 = 0.f, m1 = 0.f, m2 = 0.f, m3 = 0.f;
    for (int i = i0; i < n4; i += 4 * G) {
        float4 v = w4[i];
        m0 = fmaxf(m0, fmaxf(fmaxf(fabsf(v.x), fabsf(v.y)),
                             fmaxf(fabsf(v.z), fabsf(v.w))));
        int i1 = i + G;
        if (i1 < n4) {
            float4 u = w4[i1];
            m1 = fmaxf(m1, fmaxf(fmaxf(fabsf(u.x), fabsf(u.y)),
                                 fmaxf(fabsf(u.z), fabsf(u.w))));
        }
        int i2 = i + 2 * G;
        if (i2 < n4) {
            float4 u = w4[i2];
            m2 = fmaxf(m2, fmaxf(fmaxf(fabsf(u.x), fabsf(u.y)),
                                 fmaxf(fabsf(u.z), fabsf(u.w))));
        }
        int i3 = i + 3 * G;
        if (i3 < n4) {
            float4 u = w4[i3];
            m3 = fmaxf(m3, fmaxf(fmaxf(fabsf(u.x), fabsf(u.y)),
                                 fmaxf(fabsf(u.z), fabsf(u.w))));
        }
    }
    float m = fmaxf(fmaxf(m0, m1), fmaxf(m2, m3));
    #pragma unroll
    for (int o = 16; o; o >>= 1) m = fmaxf(m, __shfl_xor_sync(0xffffffffu, m, o));
    __shared__ float sm[8];
    int lane = threadIdx.x & 31, wid = threadIdx.x >> 5;
    if (lane == 0) sm[wid] = m;
    __syncthreads();
    if (wid == 0) {
        m = (lane < 8) ? sm[lane] : 0.0f;
        #pragma unroll
        for (int o = 4; o; o >>= 1) m = fmaxf(m, __shfl_xor_sync(0xffffffffu, m, o));
        if (lane == 0) atomicMax((int*)&g_maxabs[idx], __float_as_int(m));
    }
}

// blocks: [0,1024) wl1, [1024,1042) w2, [1042,1082) wl2, [1082] w1
__global__ void maxabs_all_k(const float* __restrict__ w1,
                             const float* __restrict__ w2,
                             const float* __restrict__ wl1,
                             const float* __restrict__ wl2) {
    int bx = blockIdx.x;
    if (bx < 1024)        maxabs_dev(wl1, (4096 * 1600) >> 2, 2, bx, 1024);
    else if (bx < 1042)   maxabs_dev(w2, (64 * 32 * 9) >> 2, 1, bx - 1024, 18);
    else if (bx < 1082)   maxabs_dev(wl2, (10 * 4096) >> 2, 3, bx - 1042, 40);
    else                  maxabs_dev(w1, (32 * 9) >> 2, 0, 0, 1);
}

// ---------------- quantization ----------------
__global__ void quant_x_k(const float* __restrict__ x, const float* __restrict__ sp) {
    float inv = 1.0f / *sp;  // s_in power of two -> exact
    const int n4 = (NB * 784) >> 2;
    const float4* x4 = (const float4*)x;
    char4* q4 = (char4*)g_qx;
    for (int i = blockIdx.x * blockDim.x + threadIdx.x; i < n4;
         i += gridDim.x * blockDim.x) {
        float4 v = x4[i];
        char4 q;
        q.x = (char)clampi((int)rintf(v.x * inv), -8, 7);
        q.y = (char)clampi((int)rintf(v.y * inv), -8, 7);
        q.z = (char)clampi((int)rintf(v.z * inv), -8, 7);
        q.w = (char)clampi((int)rintf(v.w * inv), -8, 7);
        q4[i] = q;
    }
}

// blocks: [0,2048) wl1, [2048,2208) wl2, [2208,2280) w2, [2280,2282) w1
__global__ void quant_w_k(const float* __restrict__ w1,
                          const float* __restrict__ w2,
                          const float* __restrict__ wl1,
                          const float* __restrict__ wl2) {
    int bx = blockIdx.x, tid = threadIdx.x;
    if (bx < 2048) {
        float inv = 7.0f / g_maxabs[2];
        float s = g_maxabs[2] / 7.0f;
        (void)inv;
        float rinv = 1.0f / s;
        const int n4 = (4096 * 1600) >> 2;
        const float4* w4 = (const float4*)wl1;
        char4* o4 = (char4*)g_qwl1;
        for (int i = bx * 256 + tid; i < n4; i += 2048 * 256) {
            float4 v = w4[i];
            char4 q;
            q.x = (char)clampi((int)rintf(v.x * rinv), -7, 7);
            q.y = (char)clampi((int)rintf(v.y * rinv), -7, 7);
            q.z = (char)clampi((int)rintf(v.z * rinv), -7, 7);
            q.w = (char)clampi((int)rintf(v.w * rinv), -7, 7);
            o4[i] = q;
        }
    } else if (bx < 2208) {
        float s = g_maxabs[3] / 7.0f;
        int i = (bx - 2048) * 256 + tid;
        if (i < 10 * 4096)
            g_qwl2[i] = (int8_t)clampi((int)rintf(wl2[i] / s), -7, 7);
    } else if (bx < 2280) {
        float s = g_maxabs[1] / 7.0f;
        int i = (bx - 2208) * 256 + tid;
        if (i < 64 * 9 * 32) {
            int oc = i / 288, r = i % 288;
            int pos = r >> 5, ic = r & 31;
            float v = w2[(oc * 32 + ic) * 9 + pos];
            g_qw2[i] = (int8_t)clampi((int)rintf(v / s), -7, 7);
        }
    } else {
        float s = g_maxabs[0] / 7.0f;
        int i = (bx - 2280) * 256 + tid;
        if (i < 32 * 9)
            g_qw1[i] = (int8_t)clampi((int)rintf(w1[i] / s), -7, 7);
    }
}

// ---------------- fused conv1+pool+fq  ->  conv2(IMMA)+pool+fq ----------------
// Per image (1 block, 256 threads). act1 kept in smem (stride 48); conv2's IMMA
// A-operand gathered directly from act1 by ldmatrix (K-order = (ky,kx,ic), which
// matches g_qw2 rows). C dumped to smem, then 2x2 pool + fq -> g_act2 (s8).
#define A1S 48
#define WS2 304
__global__ __launch_bounds__(256) void conv12_k(const float* __restrict__ s_in_p,
                                                const float* __restrict__ s_a1_p,
                                                const float* __restrict__ s_a2_p) {
    __shared__ __align__(16) int8_t S[35072];
    int8_t* sw2 = S;               // 64*304 = 19456
    int8_t* a1s = S + 19456;       // 8576 (178 rows x 48 max reach, padded)
    int8_t* sx  = S + 28032;       // 784
    int8_t* sw1 = S + 28816;       // 288
    int b = blockIdx.x, tid = threadIdx.x;
    int lane = tid & 31, wid = tid >> 5;

    // conv2 weights via cp.async (overlaps conv1 work)
    for (int idx = tid; idx < 1152; idx += 256) {
        int row = idx / 18, seg = idx % 18;
        CPA16(smem_u32(sw2 + row * WS2 + seg * 16),
              (const char*)g_qw2 + row * 288 + seg * 16);
    }
    CPC();
    {
        const int* gx = (const int*)(g_qx + b * 784);
        int* sxi = (int*)sx;
        for (int i = tid; i < 196; i += 256) sxi[i] = gx[i];
        const int* gw = (const int*)g_qw1;
        if (tid < 72) ((int*)sw1)[tid] = gw[tid];
    }
    __syncthreads();

    float s_in = *s_in_p, s_a1 = *s_a1_p, s_a2 = *s_a2_p;
    float mul1 = s_in * (g_maxabs[0] / 7.0f);

    // conv1 + relu-fq + pool + signed-fq -> a1s[pix*48 + oc]
    for (int o = tid; o < 32 * 169; o += 256) {
        int oc = o / 169, pix = o % 169;
        int py = pix / 13, px = pix % 13;
        int qm = 0;
        #pragma unroll
        for (int dy = 0; dy < 2; dy++)
            #pragma unroll
            for (int dx = 0; dx < 2; dx++) {
                int cy = 2 * py + dy, cx = 2 * px + dx;
                int acc = 0;
                #pragma unroll
                for (int ky = 0; ky < 3; ky++)
                    #pragma unroll
                    for (int kx = 0; kx < 3; kx++)
                        acc += (int)sx[(cy + ky) * 28 + cx + kx]
                             * (int)sw1[oc * 9 + ky * 3 + kx];
                float v = (float)acc * mul1;
                int q = clampi((int)rintf(v / s_a1), 0, 15);
                qm = max(qm, q);
            }
        int q2 = clampi((int)rintf((float)qm * s_a1 / s_in), -8, 7);
        a1s[pix * A1S + oc] = (int8_t)q2;
    }
    CPW0();
    __syncthreads();

    // conv2 IMMA: A[128 conv-pix][288] gathered from a1s, B = sw2 [64 oc][288]
    int wm = wid >> 1, wn = wid & 1;
    int c[2][4][4];
    #pragma unroll
    for (int h = 0; h < 2; h++)
        #pragma unroll
        for (int nt = 0; nt < 4; nt++)
            #pragma unroll
            for (int e = 0; e < 4; e++) c[h][nt][e] = 0;

    uint32_t bbase = smem_u32(sw2)
                   + (wn * 32 + (lane & 7) + ((lane >> 4) << 3)) * WS2
                   + (((lane >> 3) & 1) << 4);
    uint32_t abase_h[2];
    {
        int khalf = lane >> 4;
        #pragma unroll
        for (int h = 0; h < 2; h++) {
            int p = h * 64 + wm * 16 + (lane & 15);
            int cy = p / 11, cx = p % 11;
            abase_h[h] = smem_u32(a1s) + (cy * 13 + cx) * A1S + khalf * 16;
        }
    }

    #pragma unroll
    for (int h = 0; h < 2; h++) {
        #pragma unroll
        for (int ks = 0; ks < 9; ks++) {
            int ky = ks / 3, kx = ks % 3;
            uint32_t a[4];
            ldsm4(a[0], a[1], a[2], a[3], abase_h[h] + (ky * 13 + kx) * A1S);
            uint32_t bb[4][2];
            #pragma unroll
            for (int j = 0; j < 2; j++) {
                uint32_t r0, r1, r2, r3;
                ldsm4(r0, r1, r2, r3, bbase + j * 16 * WS2 + ks * 32);
                bb[2 * j][0] = r0;     bb[2 * j][1] = r1;
                bb[2 * j + 1][0] = r2; bb[2 * j + 1][1] = r3;
            }
            #pragma unroll
            for (int nt = 0; nt < 4; nt++)
                imma16832(c[h][nt], a, bb[nt]);
        }
    }
    __syncthreads();   // everyone done reading sw2/a1s -> reuse S as C

    int* Cs = (int*)S;  // [128 pix][68] int
    #pragma unroll
    for (int h = 0; h < 2; h++) {
        int row = h * 64 + wm * 16 + (lane >> 2);
        #pragma unroll
        for (int nt = 0; nt < 4; nt++) {
            int col = wn * 32 + nt * 8 + ((lane & 3) << 1);
            int2 v0 = make_int2(c[h][nt][0], c[h][nt][1]);
            int2 v1 = make_int2(c[h][nt][2], c[h][nt][3]);
            *(int2*)(Cs + row * 68 + col) = v0;
            *(int2*)(Cs + (row + 8) * 68 + col) = v1;
        }
    }
    __syncthreads();

    float mul2 = s_in * (g_maxabs[1] / 7.0f);
    for (int o = tid; o < 1600; o += 256) {
        int oc = o / 25, p = o % 25;
        int py = p / 5, px = p % 5;
        int qm = 0;
        #pragma unroll
        for (int dy = 0; dy < 2; dy++)
            #pragma unroll
            for (int dx = 0; dx < 2; dx++) {
                int cp = (2 * py + dy) * 11 + 2 * px + dx;
                int acc = Cs[cp * 68 + oc];
                float v = (float)acc * mul2;
                int q = clampi((int)rintf(v / s_a2), 0, 15);
                qm = max(qm, q);
            }
        int q2 = clampi((int)rintf((float)qm * s_a2 / s_in), -8, 7);
        g_act2[b * 1600 + o] = (int8_t)q2;
    }
}

// ---------------- fc1: s8 IMMA GEMM [1024,1600] x [4096,1600]^T ----------------
// BM=128, BN=128, BK=64 bytes, 256 threads (8 warps = 2m x 4n), warp tile 64x32.
__global__ __launch_bounds__(256) void fc1_imma_k(const float* __restrict__ s_in_p,
                                                  const float* __restrict__ s_a3_p) {
    __shared__ __align__(16) int8_t sA[2][128 * 80];
    __shared__ __align__(16) int8_t sB[2][128 * 80];
    const int BUFB = 128 * 80;

    int tid = threadIdx.x, lane = tid & 31, wid = tid >> 5;
    int wm = wid >> 2, wn = wid & 3;
    int bm = blockIdx.y, bn = blockIdx.x;

    int lrow = tid >> 2, lseg = tid & 3;
    const char* gA0 = (const char*)g_act2 + (size_t)(bm * 128 + lrow) * 1600 + lseg * 16;
    const char* gB0 = (const char*)g_qwl1 + (size_t)(bn * 128 + lrow) * 1600 + lseg * 16;
    uint32_t smA0 = smem_u32(&sA[0][0]) + lrow * 80 + lseg * 16;
    uint32_t smB0 = smem_u32(&sB[0][0]) + lrow * 80 + lseg * 16;

    int c[4][4][4];
    #pragma unroll
    for (int i = 0; i < 4; i++)
        #pragma unroll
        for (int j = 0; j < 4; j++)
            #pragma unroll
            for (int e = 0; e < 4; e++) c[i][j][e] = 0;

    CPA16(smA0, gA0);
    CPA16(smA0 + 64 * 80, gA0 + (size_t)64 * 1600);
    CPA16(smB0, gB0);
    CPA16(smB0 + 64 * 80, gB0 + (size_t)64 * 1600);
    CPC(); CPW0();
    __syncthreads();

    uint32_t saL = smem_u32(&sA[0][0]) + (wm * 64 + (lane & 15)) * 80 + ((lane >> 4) << 4);
    uint32_t sbL = smem_u32(&sB[0][0])
                 + (wn * 32 + (lane & 7) + ((lane >> 4) << 3)) * 80
                 + (((lane >> 3) & 1) << 4);

    int buf = 0;
    for (int kt = 0; kt < 25; kt++) {
        if (kt < 24) {
            int nb = buf ^ 1;
            const char* ga = gA0 + (kt + 1) * 64;
            const char* gb = gB0 + (kt + 1) * 64;
            uint32_t da = smA0 + nb * BUFB, db = smB0 + nb * BUFB;
            CPA16(da, ga);
            CPA16(da + 64 * 80, ga + (size_t)64 * 1600);
            CPA16(db, gb);
            CPA16(db + 64 * 80, gb + (size_t)64 * 1600);
            CPC();
        }
        uint32_t sa = saL + buf * BUFB;
        uint32_t sb = sbL + buf * BUFB;
        #pragma unroll
        for (int ks = 0; ks < 2; ks++) {
            uint32_t a[4][4], bb[4][2];
            #pragma unroll
            for (int mt = 0; mt < 4; mt++)
                ldsm4(a[mt][0], a[mt][1], a[mt][2], a[mt][3],
                      sa + mt * 16 * 80 + ks * 32);
            #pragma unroll
            for (int j = 0; j < 2; j++) {
                uint32_t r0, r1, r2, r3;
                ldsm4(r0, r1, r2, r3, sb + j * 16 * 80 + ks * 32);
                bb[2 * j][0] = r0;     bb[2 * j][1] = r1;
                bb[2 * j + 1][0] = r2; bb[2 * j + 1][1] = r3;
            }
            #pragma unroll
            for (int mt = 0; mt < 4; mt++)
                #pragma unroll
                for (int nt = 0; nt < 4; nt++)
                    imma16832(c[mt][nt], a[mt], bb[nt]);
        }
        if (kt < 24) {
            CPW0();
            __syncthreads();
            buf ^= 1;
        }
    }

    float s_in = *s_in_p, s_a3 = *s_a3_p;
    float mul = s_in * (g_maxabs[2] / 7.0f);
    float isa3 = 1.0f / s_a3;  // power of two -> exact
    int r0 = bm * 128 + wm * 64 + (lane >> 2);
    int c0 = bn * 128 + wn * 32 + ((lane & 3) << 1);
    #pragma unroll
    for (int mt = 0; mt < 4; mt++) {
        #pragma unroll
        for (int nt = 0; nt < 4; nt++) {
            int rr = r0 + mt * 16, cc = c0 + nt * 8;
            int* cf = c[mt][nt];
            uchar2 lo, hi;
            lo.x = (uint8_t)clampi((int)rintf((float)cf[0] * mul * isa3), 0, 15);
            lo.y = (uint8_t)clampi((int)rintf((float)cf[1] * mul * isa3), 0, 15);
            hi.x = (uint8_t)clampi((int)rintf((float)cf[2] * mul * isa3), 0, 15);
            hi.y = (uint8_t)clampi((int)rintf((float)cf[3] * mul * isa3), 0, 15);
            *(uchar2*)(g_act3 + rr * 4096 + cc) = lo;
            *(uchar2*)(g_act3 + (rr + 8) * 4096 + cc) = hi;
        }
    }
}

// ---------------- fc2: [1024,4096] x [10,4096]^T -> out ----------------
__global__ void fc2_k(const float* __restrict__ s_a3_p, float* __restrict__ out) {
    int b = blockIdx.x;
    int wj = threadIdx.x >> 5, lane = threadIdx.x & 31;
    const int* ar = (const int*)(g_act3 + b * 4096);
    const int* wr = (const int*)(g_qwl2 + wj * 4096);
    int acc = 0;
    for (int t = lane; t < 1024; t += 32)
        acc = __dp4a(ar[t], wr[t], acc);
    #pragma unroll
    for (int o = 16; o; o >>= 1) acc += __shfl_xor_sync(0xffffffffu, acc, o);
    if (lane == 0)
        out[b * 10 + wj] = (float)acc * (*s_a3_p) * (g_maxabs[3] / 7.0f);
}

// ---------------- launcher ----------------
extern "C" void kernel_launch(void* const* d_in, const int* in_sizes, int n_in,
                              void* d_out, int out_size) {
    const float* x    = (const float*)d_in[0];
    const float* w1   = (const float*)d_in[1];
    const float* w2   = (const float*)d_in[2];
    const float* wl1  = (const float*)d_in[3];
    const float* wl2  = (const float*)d_in[4];
    const float* s_in = (const float*)d_in[5];
    const float* s_a1 = (const float*)d_in[6];
    const float* s_a2 = (const float*)d_in[7];
    const float* s_a3 = (const float*)d_in[8];
    float* out = (float*)d_out;

    reset_k<<<1, 32>>>();
    quant_x_k<<<392, 256>>>(x, s_in);
    maxabs_all_k<<<1083, 256>>>(w1, w2, wl1, wl2);
    quant_w_k<<<2282, 256>>>(w1, w2, wl1, wl2);
    conv12_k<<<1024, 256>>>(s_in, s_a1, s_a2);
    fc1_imma_k<<<dim3(32, 8), 256>>>(s_in, s_a3);
    fc2_k<<<1024, 320>>>(s_a3, out);
}

// round 9
// speedup vs baseline: 2.4091x; 1.0804x over previous
#include <cuda_runtime.h>
#include <cuda_bf16.h>
#include <stdint.h>

#define NB 1024

// ---------------- scratch (no allocations allowed) ----------------
__device__ float g_maxabs[4];                           // zero-init; reset by tail kernel
__device__ __align__(16) int8_t g_qx  [NB * 784];       // quantized input q
__device__ __align__(16) int8_t g_qw1 [32 * 9];         // [oc][kpos]
__device__ __align__(16) int8_t g_qw2 [64 * 9 * 32];    // [oc][kpos 9][ic 32] rows of 288
__device__ __align__(16) int8_t g_act2[NB * 1600];      // fc1 A (s8 q) [b][oc*25+p]
__device__ __align__(16) int8_t g_qwl1[4096 * 1600];    // fc1 B (s8 q) [n][k]
__device__ __align__(16) int8_t g_act3[NB * 4096];      // fc1 output q (0..15)
__device__ __align__(16) int8_t g_qwl2[10 * 4096];      // [n][k]

__device__ __forceinline__ int clampi(int v, int lo, int hi) {
    return max(lo, min(hi, v));
}
__device__ __forceinline__ uint32_t smem_u32(const void* p) {
    return (uint32_t)__cvta_generic_to_shared(p);
}
__device__ __forceinline__ void ldsm4(uint32_t& r0, uint32_t& r1, uint32_t& r2,
                                      uint32_t& r3, uint32_t a) {
    asm volatile("ldmatrix.sync.aligned.m8n8.x4.shared.b16 {%0,%1,%2,%3}, [%4];\n"
                 : "=r"(r0), "=r"(r1), "=r"(r2), "=r"(r3) : "r"(a));
}
__device__ __forceinline__ void imma16832(int* c, const uint32_t* a, const uint32_t* b) {
    asm volatile(
        "mma.sync.aligned.m16n8k32.row.col.s32.s8.s8.s32 "
        "{%0,%1,%2,%3},{%4,%5,%6,%7},{%8,%9},{%0,%1,%2,%3};\n"
        : "+r"(c[0]), "+r"(c[1]), "+r"(c[2]), "+r"(c[3])
        : "r"(a[0]), "r"(a[1]), "r"(a[2]), "r"(a[3]), "r"(b[0]), "r"(b[1]));
}
#define CPA16(dst, src) \
    asm volatile("cp.async.cg.shared.global [%0], [%1], 16;\n" ::"r"(dst), "l"(src))
#define CPC()  asm volatile("cp.async.commit_group;\n")
#define CPW0() asm volatile("cp.async.wait_group 0;\n")

// ---------------- maxabs (+ fused quant_x) ----------------
__device__ void maxabs_dev(const float* __restrict__ w, int n4, int idx,
                           int bid, int nblocks) {
    const float4* w4 = (const float4*)w;
    int G = nblocks * 256;
    int i0 = bid * 256 + threadIdx.x;
    float m0 = 0.f, m1 = 0.f, m2 = 0.f, m3 = 0.f;
    for (int i = i0; i < n4; i += 4 * G) {
        float4 v = w4[i];
        m0 = fmaxf(m0, fmaxf(fmaxf(fabsf(v.x), fabsf(v.y)),
                             fmaxf(fabsf(v.z), fabsf(v.w))));
        int i1 = i + G;
        if (i1 < n4) {
            float4 u = w4[i1];
            m1 = fmaxf(m1, fmaxf(fmaxf(fabsf(u.x), fabsf(u.y)),
                                 fmaxf(fabsf(u.z), fabsf(u.w))));
        }
        int i2 = i + 2 * G;
        if (i2 < n4) {
            float4 u = w4[i2];
            m2 = fmaxf(m2, fmaxf(fmaxf(fabsf(u.x), fabsf(u.y)),
                                 fmaxf(fabsf(u.z), fabsf(u.w))));
        }
        int i3 = i + 3 * G;
        if (i3 < n4) {
            float4 u = w4[i3];
            m3 = fmaxf(m3, fmaxf(fmaxf(fabsf(u.x), fabsf(u.y)),
                                 fmaxf(fabsf(u.z), fabsf(u.w))));
        }
    }
    float m = fmaxf(fmaxf(m0, m1), fmaxf(m2, m3));
    #pragma unroll
    for (int o = 16; o; o >>= 1) m = fmaxf(m, __shfl_xor_sync(0xffffffffu, m, o));
    __shared__ float sm[8];
    int lane = threadIdx.x & 31, wid = threadIdx.x >> 5;
    if (lane == 0) sm[wid] = m;
    __syncthreads();
    if (wid == 0) {
        m = (lane < 8) ? sm[lane] : 0.0f;
        #pragma unroll
        for (int o = 4; o; o >>= 1) m = fmaxf(m, __shfl_xor_sync(0xffffffffu, m, o));
        if (lane == 0) atomicMax((int*)&g_maxabs[idx], __float_as_int(m));
    }
}

// blocks: [0,1024) wl1 max, [1024,1042) w2, [1042,1082) wl2, [1082] w1,
//         [1083, 1475) quant_x (each thread covers 2 elements: i, i+100352)
__global__ void prep1_k(const float* __restrict__ w1,
                        const float* __restrict__ w2,
                        const float* __restrict__ wl1,
                        const float* __restrict__ wl2,
                        const float* __restrict__ x,
                        const float* __restrict__ s_in_p) {
    int bx = blockIdx.x;
    if (bx < 1024)        maxabs_dev(wl1, (4096 * 1600) >> 2, 2, bx, 1024);
    else if (bx < 1042)   maxabs_dev(w2, (64 * 32 * 9) >> 2, 1, bx - 1024, 18);
    else if (bx < 1082)   maxabs_dev(wl2, (10 * 4096) >> 2, 3, bx - 1042, 40);
    else if (bx == 1082)  maxabs_dev(w1, (32 * 9) >> 2, 0, 0, 1);
    else {
        float inv = 1.0f / *s_in_p;  // s_in power of two -> exact
        const int n4 = (NB * 784) >> 2;  // 200704
        const int half = 392 * 256;      // 100352
        const float4* x4 = (const float4*)x;
        char4* q4 = (char4*)g_qx;
        int i = (bx - 1083) * 256 + (int)threadIdx.x;
        #pragma unroll
        for (int rep = 0; rep < 2; rep++) {
            int ii = i + rep * half;
            if (ii < n4) {
                float4 v = x4[ii];
                char4 q;
                q.x = (char)clampi((int)rintf(v.x * inv), -8, 7);
                q.y = (char)clampi((int)rintf(v.y * inv), -8, 7);
                q.z = (char)clampi((int)rintf(v.z * inv), -8, 7);
                q.w = (char)clampi((int)rintf(v.w * inv), -8, 7);
                q4[ii] = q;
            }
        }
    }
}

// blocks: [0,2048) wl1, [2048,2208) wl2, [2208,2280) w2, [2280,2282) w1
__global__ void quant_w_k(const float* __restrict__ w1,
                          const float* __restrict__ w2,
                          const float* __restrict__ wl1,
                          const float* __restrict__ wl2) {
    int bx = blockIdx.x, tid = threadIdx.x;
    if (bx < 2048) {
        float rinv = 1.0f / (g_maxabs[2] / 7.0f);
        const int n4 = (4096 * 1600) >> 2;
        const float4* w4 = (const float4*)wl1;
        char4* o4 = (char4*)g_qwl1;
        for (int i = bx * 256 + tid; i < n4; i += 2048 * 256) {
            float4 v = w4[i];
            char4 q;
            q.x = (char)clampi((int)rintf(v.x * rinv), -7, 7);
            q.y = (char)clampi((int)rintf(v.y * rinv), -7, 7);
            q.z = (char)clampi((int)rintf(v.z * rinv), -7, 7);
            q.w = (char)clampi((int)rintf(v.w * rinv), -7, 7);
            o4[i] = q;
        }
    } else if (bx < 2208) {
        float s = g_maxabs[3] / 7.0f;
        int i = (bx - 2048) * 256 + tid;
        if (i < 10 * 4096)
            g_qwl2[i] = (int8_t)clampi((int)rintf(wl2[i] / s), -7, 7);
    } else if (bx < 2280) {
        float s = g_maxabs[1] / 7.0f;
        int i = (bx - 2208) * 256 + tid;
        if (i < 64 * 9 * 32) {
            int oc = i / 288, r = i % 288;
            int pos = r >> 5, ic = r & 31;
            float v = w2[(oc * 32 + ic) * 9 + pos];
            g_qw2[i] = (int8_t)clampi((int)rintf(v / s), -7, 7);
        }
    } else {
        float s = g_maxabs[0] / 7.0f;
        int i = (bx - 2280) * 256 + tid;
        if (i < 32 * 9)
            g_qw1[i] = (int8_t)clampi((int)rintf(w1[i] / s), -7, 7);
    }
}

// ---------------- fused conv1+pool+fq  ->  conv2(IMMA)+pool+fq ----------------
#define A1S 48
#define WS2 304
__global__ __launch_bounds__(256) void conv12_k(const float* __restrict__ s_in_p,
                                                const float* __restrict__ s_a1_p,
                                                const float* __restrict__ s_a2_p) {
    __shared__ __align__(16) int8_t S[35072];
    int8_t* sw2 = S;               // 64*304 = 19456
    int8_t* a1s = S + 19456;       // act1 tile (stride 48)
    int8_t* sx  = S + 28032;       // 784
    int8_t* sw1 = S + 28816;       // 288
    int b = blockIdx.x, tid = threadIdx.x;
    int lane = tid & 31, wid = tid >> 5;

    for (int idx = tid; idx < 1152; idx += 256) {
        int row = idx / 18, seg = idx % 18;
        CPA16(smem_u32(sw2 + row * WS2 + seg * 16),
              (const char*)g_qw2 + row * 288 + seg * 16);
    }
    CPC();
    {
        const int* gx = (const int*)(g_qx + b * 784);
        int* sxi = (int*)sx;
        for (int i = tid; i < 196; i += 256) sxi[i] = gx[i];
        const int* gw = (const int*)g_qw1;
        if (tid < 72) ((int*)sw1)[tid] = gw[tid];
    }
    __syncthreads();

    float s_in = *s_in_p, s_a1 = *s_a1_p, s_a2 = *s_a2_p;
    float mul1 = s_in * (g_maxabs[0] / 7.0f);

    for (int o = tid; o < 32 * 169; o += 256) {
        int oc = o / 169, pix = o % 169;
        int py = pix / 13, px = pix % 13;
        int qm = 0;
        #pragma unroll
        for (int dy = 0; dy < 2; dy++)
            #pragma unroll
            for (int dx = 0; dx < 2; dx++) {
                int cy = 2 * py + dy, cx = 2 * px + dx;
                int acc = 0;
                #pragma unroll
                for (int ky = 0; ky < 3; ky++)
                    #pragma unroll
                    for (int kx = 0; kx < 3; kx++)
                        acc += (int)sx[(cy + ky) * 28 + cx + kx]
                             * (int)sw1[oc * 9 + ky * 3 + kx];
                float v = (float)acc * mul1;
                int q = clampi((int)rintf(v / s_a1), 0, 15);
                qm = max(qm, q);
            }
        int q2 = clampi((int)rintf((float)qm * s_a1 / s_in), -8, 7);
        a1s[pix * A1S + oc] = (int8_t)q2;
    }
    CPW0();
    __syncthreads();

    int wm = wid >> 1, wn = wid & 1;
    int c[2][4][4];
    #pragma unroll
    for (int h = 0; h < 2; h++)
        #pragma unroll
        for (int nt = 0; nt < 4; nt++)
            #pragma unroll
            for (int e = 0; e < 4; e++) c[h][nt][e] = 0;

    uint32_t bbase = smem_u32(sw2)
                   + (wn * 32 + (lane & 7) + ((lane >> 4) << 3)) * WS2
                   + (((lane >> 3) & 1) << 4);
    uint32_t abase_h[2];
    {
        int khalf = lane >> 4;
        #pragma unroll
        for (int h = 0; h < 2; h++) {
            int p = h * 64 + wm * 16 + (lane & 15);
            int cy = p / 11, cx = p % 11;
            abase_h[h] = smem_u32(a1s) + (cy * 13 + cx) * A1S + khalf * 16;
        }
    }

    #pragma unroll
    for (int h = 0; h < 2; h++) {
        #pragma unroll
        for (int ks = 0; ks < 9; ks++) {
            int ky = ks / 3, kx = ks % 3;
            uint32_t a[4];
            ldsm4(a[0], a[1], a[2], a[3], abase_h[h] + (ky * 13 + kx) * A1S);
            uint32_t bb[4][2];
            #pragma unroll
            for (int j = 0; j < 2; j++) {
                uint32_t r0, r1, r2, r3;
                ldsm4(r0, r1, r2, r3, bbase + j * 16 * WS2 + ks * 32);
                bb[2 * j][0] = r0;     bb[2 * j][1] = r1;
                bb[2 * j + 1][0] = r2; bb[2 * j + 1][1] = r3;
            }
            #pragma unroll
            for (int nt = 0; nt < 4; nt++)
                imma16832(c[h][nt], a, bb[nt]);
        }
    }
    __syncthreads();

    int* Cs = (int*)S;  // [128 pix][68] int
    #pragma unroll
    for (int h = 0; h < 2; h++) {
        int row = h * 64 + wm * 16 + (lane >> 2);
        #pragma unroll
        for (int nt = 0; nt < 4; nt++) {
            int col = wn * 32 + nt * 8 + ((lane & 3) << 1);
            int2 v0 = make_int2(c[h][nt][0], c[h][nt][1]);
            int2 v1 = make_int2(c[h][nt][2], c[h][nt][3]);
            *(int2*)(Cs + row * 68 + col) = v0;
            *(int2*)(Cs + (row + 8) * 68 + col) = v1;
        }
    }
    __syncthreads();

    float mul2 = s_in * (g_maxabs[1] / 7.0f);
    for (int o = tid; o < 1600; o += 256) {
        int oc = o / 25, p = o % 25;
        int py = p / 5, px = p % 5;
        int qm = 0;
        #pragma unroll
        for (int dy = 0; dy < 2; dy++)
            #pragma unroll
            for (int dx = 0; dx < 2; dx++) {
                int cp = (2 * py + dy) * 11 + 2 * px + dx;
                int acc = Cs[cp * 68 + oc];
                float v = (float)acc * mul2;
                int q = clampi((int)rintf(v / s_a2), 0, 15);
                qm = max(qm, q);
            }
        int q2 = clampi((int)rintf((float)qm * s_a2 / s_in), -8, 7);
        g_act2[b * 1600 + o] = (int8_t)q2;
    }
}

// ---------------- fc1: s8 IMMA GEMM, 64x64 tiles for wave balance ----------------
// Grid (64, 16) = 1024 CTAs, 128 threads (4 warps 2x2), warp tile 32x32, BK=64.
__global__ __launch_bounds__(128) void fc1_imma_k(const float* __restrict__ s_in_p,
                                                  const float* __restrict__ s_a3_p) {
    __shared__ __align__(16) int8_t sA[2][64 * 80];
    __shared__ __align__(16) int8_t sB[2][64 * 80];
    const int BUFB = 64 * 80;

    int tid = threadIdx.x, lane = tid & 31, wid = tid >> 5;
    int wm = wid >> 1, wn = wid & 1;
    int bm = blockIdx.y, bn = blockIdx.x;

    // loader: 64 rows; each thread covers 2 adjacent 16B segs
    int lrow = tid >> 1, lseg2 = (tid & 1) << 1;
    const char* gA0 = (const char*)g_act2 + (size_t)(bm * 64 + lrow) * 1600 + lseg2 * 16;
    const char* gB0 = (const char*)g_qwl1 + (size_t)(bn * 64 + lrow) * 1600 + lseg2 * 16;
    uint32_t smA0 = smem_u32(&sA[0][0]) + lrow * 80 + lseg2 * 16;
    uint32_t smB0 = smem_u32(&sB[0][0]) + lrow * 80 + lseg2 * 16;

    int c[2][4][4];
    #pragma unroll
    for (int i = 0; i < 2; i++)
        #pragma unroll
        for (int j = 0; j < 4; j++)
            #pragma unroll
            for (int e = 0; e < 4; e++) c[i][j][e] = 0;

    CPA16(smA0, gA0);
    CPA16(smA0 + 16, gA0 + 16);
    CPA16(smB0, gB0);
    CPA16(smB0 + 16, gB0 + 16);
    CPC(); CPW0();
    __syncthreads();

    uint32_t saL = smem_u32(&sA[0][0]) + (wm * 32 + (lane & 15)) * 80 + ((lane >> 4) << 4);
    uint32_t sbL = smem_u32(&sB[0][0])
                 + (wn * 32 + (lane & 7) + ((lane >> 4) << 3)) * 80
                 + (((lane >> 3) & 1) << 4);

    int buf = 0;
    for (int kt = 0; kt < 25; kt++) {
        if (kt < 24) {
            int nb = buf ^ 1;
            const char* ga = gA0 + (kt + 1) * 64;
            const char* gb = gB0 + (kt + 1) * 64;
            uint32_t da = smA0 + nb * BUFB, db = smB0 + nb * BUFB;
            CPA16(da, ga);
            CPA16(da + 16, ga + 16);
            CPA16(db, gb);
            CPA16(db + 16, gb + 16);
            CPC();
        }
        uint32_t sa = saL + buf * BUFB;
        uint32_t sb = sbL + buf * BUFB;
        #pragma unroll
        for (int ks = 0; ks < 2; ks++) {
            uint32_t a[2][4], bb[4][2];
            #pragma unroll
            for (int mt = 0; mt < 2; mt++)
                ldsm4(a[mt][0], a[mt][1], a[mt][2], a[mt][3],
                      sa + mt * 16 * 80 + ks * 32);
            #pragma unroll
            for (int j = 0; j < 2; j++) {
                uint32_t r0, r1, r2, r3;
                ldsm4(r0, r1, r2, r3, sb + j * 16 * 80 + ks * 32);
                bb[2 * j][0] = r0;     bb[2 * j][1] = r1;
                bb[2 * j + 1][0] = r2; bb[2 * j + 1][1] = r3;
            }
            #pragma unroll
            for (int mt = 0; mt < 2; mt++)
                #pragma unroll
                for (int nt = 0; nt < 4; nt++)
                    imma16832(c[mt][nt], a[mt], bb[nt]);
        }
        if (kt < 24) {
            CPW0();
            __syncthreads();
            buf ^= 1;
        }
    }

    float s_in = *s_in_p, s_a3 = *s_a3_p;
    float mul = s_in * (g_maxabs[2] / 7.0f);
    float isa3 = 1.0f / s_a3;  // power of two -> exact
    int r0 = bm * 64 + wm * 32 + (lane >> 2);
    int c0 = bn * 64 + wn * 32 + ((lane & 3) << 1);
    #pragma unroll
    for (int mt = 0; mt < 2; mt++) {
        #pragma unroll
        for (int nt = 0; nt < 4; nt++) {
            int rr = r0 + mt * 16, cc = c0 + nt * 8;
            int* cf = c[mt][nt];
            uchar2 lo, hi;
            lo.x = (uint8_t)clampi((int)rintf((float)cf[0] * mul * isa3), 0, 15);
            lo.y = (uint8_t)clampi((int)rintf((float)cf[1] * mul * isa3), 0, 15);
            hi.x = (uint8_t)clampi((int)rintf((float)cf[2] * mul * isa3), 0, 15);
            hi.y = (uint8_t)clampi((int)rintf((float)cf[3] * mul * isa3), 0, 15);
            *(uchar2*)(g_act3 + rr * 4096 + cc) = lo;
            *(uchar2*)(g_act3 + (rr + 8) * 4096 + cc) = hi;
        }
    }
}

// ---------------- fc2: [1024,4096] x [10,4096]^T -> out ----------------
__global__ void fc2_k(const float* __restrict__ s_a3_p, float* __restrict__ out) {
    int b = blockIdx.x;
    int wj = threadIdx.x >> 5, lane = threadIdx.x & 31;
    const int* ar = (const int*)(g_act3 + b * 4096);
    const int* wr = (const int*)(g_qwl2 + wj * 4096);
    int acc = 0;
    for (int t = lane; t < 1024; t += 32)
        acc = __dp4a(ar[t], wr[t], acc);
    #pragma unroll
    for (int o = 16; o; o >>= 1) acc += __shfl_xor_sync(0xffffffffu, acc, o);
    if (lane == 0)
        out[b * 10 + wj] = (float)acc * (*s_a3_p) * (g_maxabs[3] / 7.0f);
}

// reset scales for the next replay (statics are zero-init for the first call)
__global__ void reset_tail_k() {
    if (threadIdx.x < 4) g_maxabs[threadIdx.x] = 0.0f;
}

// ---------------- launcher ----------------
extern "C" void kernel_launch(void* const* d_in, const int* in_sizes, int n_in,
                              void* d_out, int out_size) {
    const float* x    = (const float*)d_in[0];
    const float* w1   = (const float*)d_in[1];
    const float* w2   = (const float*)d_in[2];
    const float* wl1  = (const float*)d_in[3];
    const float* wl2  = (const float*)d_in[4];
    const float* s_in = (const float*)d_in[5];
    const float* s_a1 = (const float*)d_in[6];
    const float* s_a2 = (const float*)d_in[7];
    const float* s_a3 = (const float*)d_in[8];
    float* out = (float*)d_out;

    prep1_k<<<1475, 256>>>(w1, w2, wl1, wl2, x, s_in);   // maxabs + quant_x
    quant_w_k<<<2282, 256>>>(w1, w2, wl1, wl2);
    conv12_k<<<1024, 256>>>(s_in, s_a1, s_a2);
    fc1_imma_k<<<dim3(64, 16), 128>>>(s_in, s_a3);       // 4th launch -> ncu capture
    fc2_k<<<1024, 320>>>(s_a3, out);
    reset_tail_k<<<1, 32>>>();
}

// round 11
// speedup vs baseline: 3.1318x; 1.3000x over previous
#include <cuda_runtime.h>
#include <cuda_bf16.h>
#include <stdint.h>

#define NB 1024

// ---------------- scratch (no allocations allowed) ----------------
__device__ float g_maxabs[4];                           // zero-init; reset by fc2 tail
__device__ int   g_cnt2;                                // fc2 completion ticket
__device__ __align__(16) int8_t g_qx  [NB * 784];       // quantized input q
__device__ __align__(16) int8_t g_qw1 [32 * 9];         // [oc][kpos]
__device__ __align__(16) int8_t g_qw2 [64 * 9 * 32];    // [oc][kpos 9][ic 32] rows of 288
__device__ __align__(16) int8_t g_act2[NB * 1600];      // fc1 A (s8 q) [b][oc*25+p]
__device__ __align__(16) int8_t g_qwl1[4096 * 1600];    // fc1 B (s8 q) [n][k]
__device__ __align__(16) int8_t g_act3[NB * 4096];      // fc1 output q (0..15)
__device__ __align__(16) int8_t g_qwl2[10 * 4096];      // [n][k]

__device__ __forceinline__ int clampi(int v, int lo, int hi) {
    return max(lo, min(hi, v));
}
__device__ __forceinline__ int dp4(uint32_t a, uint32_t b, int c) {
    return __dp4a((int)a, (int)b, c);   // signed byte dot-product
}
__device__ __forceinline__ uint32_t smem_u32(const void* p) {
    return (uint32_t)__cvta_generic_to_shared(p);
}
__device__ __forceinline__ void ldsm4(uint32_t& r0, uint32_t& r1, uint32_t& r2,
                                      uint32_t& r3, uint32_t a) {
    asm volatile("ldmatrix.sync.aligned.m8n8.x4.shared.b16 {%0,%1,%2,%3}, [%4];\n"
                 : "=r"(r0), "=r"(r1), "=r"(r2), "=r"(r3) : "r"(a));
}
__device__ __forceinline__ void imma16832(int* c, const uint32_t* a, const uint32_t* b) {
    asm volatile(
        "mma.sync.aligned.m16n8k32.row.col.s32.s8.s8.s32 "
        "{%0,%1,%2,%3},{%4,%5,%6,%7},{%8,%9},{%0,%1,%2,%3};\n"
        : "+r"(c[0]), "+r"(c[1]), "+r"(c[2]), "+r"(c[3])
        : "r"(a[0]), "r"(a[1]), "r"(a[2]), "r"(a[3]), "r"(b[0]), "r"(b[1]));
}
#define CPA16(dst, src) \
    asm volatile("cp.async.cg.shared.global [%0], [%1], 16;\n" ::"r"(dst), "l"(src))
#define CPC()  asm volatile("cp.async.commit_group;\n")
#define CPW0() asm volatile("cp.async.wait_group 0;\n")

// ---------------- maxabs (+ fused quant_x) ----------------
__device__ void maxabs_dev(const float* __restrict__ w, int n4, int idx,
                           int bid, int nblocks) {
    const float4* w4 = (const float4*)w;
    int G = nblocks * 256;
    int i0 = bid * 256 + threadIdx.x;
    float m0 = 0.f, m1 = 0.f, m2 = 0.f, m3 = 0.f;
    for (int i = i0; i < n4; i += 4 * G) {
        float4 v = w4[i];
        m0 = fmaxf(m0, fmaxf(fmaxf(fabsf(v.x), fabsf(v.y)),
                             fmaxf(fabsf(v.z), fabsf(v.w))));
        int i1 = i + G;
        if (i1 < n4) {
            float4 u = w4[i1];
            m1 = fmaxf(m1, fmaxf(fmaxf(fabsf(u.x), fabsf(u.y)),
                                 fmaxf(fabsf(u.z), fabsf(u.w))));
        }
        int i2 = i + 2 * G;
        if (i2 < n4) {
            float4 u = w4[i2];
            m2 = fmaxf(m2, fmaxf(fmaxf(fabsf(u.x), fabsf(u.y)),
                                 fmaxf(fabsf(u.z), fabsf(u.w))));
        }
        int i3 = i + 3 * G;
        if (i3 < n4) {
            float4 u = w4[i3];
            m3 = fmaxf(m3, fmaxf(fmaxf(fabsf(u.x), fabsf(u.y)),
                                 fmaxf(fabsf(u.z), fabsf(u.w))));
        }
    }
    float m = fmaxf(fmaxf(m0, m1), fmaxf(m2, m3));
    #pragma unroll
    for (int o = 16; o; o >>= 1) m = fmaxf(m, __shfl_xor_sync(0xffffffffu, m, o));
    __shared__ float sm[8];
    int lane = threadIdx.x & 31, wid = threadIdx.x >> 5;
    if (lane == 0) sm[wid] = m;
    __syncthreads();
    if (wid == 0) {
        m = (lane < 8) ? sm[lane] : 0.0f;
        #pragma unroll
        for (int o = 4; o; o >>= 1) m = fmaxf(m, __shfl_xor_sync(0xffffffffu, m, o));
        if (lane == 0) atomicMax((int*)&g_maxabs[idx], __float_as_int(m));
    }
}

// blocks: [0,1024) wl1 max, [1024,1042) w2, [1042,1082) wl2, [1082] w1,
//         [1083, 1475) quant_x (each thread covers 2 elements: i, i+100352)
__global__ void prep1_k(const float* __restrict__ w1,
                        const float* __restrict__ w2,
                        const float* __restrict__ wl1,
                        const float* __restrict__ wl2,
                        const float* __restrict__ x,
                        const float* __restrict__ s_in_p) {
    int bx = blockIdx.x;
    if (bx < 1024)        maxabs_dev(wl1, (4096 * 1600) >> 2, 2, bx, 1024);
    else if (bx < 1042)   maxabs_dev(w2, (64 * 32 * 9) >> 2, 1, bx - 1024, 18);
    else if (bx < 1082)   maxabs_dev(wl2, (10 * 4096) >> 2, 3, bx - 1042, 40);
    else if (bx == 1082)  maxabs_dev(w1, (32 * 9) >> 2, 0, 0, 1);
    else {
        float inv = 1.0f / *s_in_p;  // s_in power of two -> exact
        const int n4 = (NB * 784) >> 2;  // 200704
        const int half = 392 * 256;      // 100352
        const float4* x4 = (const float4*)x;
        char4* q4 = (char4*)g_qx;
        int i = (bx - 1083) * 256 + (int)threadIdx.x;
        #pragma unroll
        for (int rep = 0; rep < 2; rep++) {
            int ii = i + rep * half;
            if (ii < n4) {
                float4 v = x4[ii];
                char4 q;
                q.x = (char)clampi((int)rintf(v.x * inv), -8, 7);
                q.y = (char)clampi((int)rintf(v.y * inv), -8, 7);
                q.z = (char)clampi((int)rintf(v.z * inv), -8, 7);
                q.w = (char)clampi((int)rintf(v.w * inv), -8, 7);
                q4[ii] = q;
            }
        }
    }
}

// blocks: [0,2048) wl1, [2048,2208) wl2, [2208,2280) w2, [2280,2282) w1
__global__ void quant_w_k(const float* __restrict__ w1,
                          const float* __restrict__ w2,
                          const float* __restrict__ wl1,
                          const float* __restrict__ wl2) {
    int bx = blockIdx.x, tid = threadIdx.x;
    if (bx < 2048) {
        float rinv = 1.0f / (g_maxabs[2] / 7.0f);
        const int n4 = (4096 * 1600) >> 2;
        const float4* w4 = (const float4*)wl1;
        char4* o4 = (char4*)g_qwl1;
        for (int i = bx * 256 + tid; i < n4; i += 2048 * 256) {
            float4 v = w4[i];
            char4 q;
            q.x = (char)clampi((int)rintf(v.x * rinv), -7, 7);
            q.y = (char)clampi((int)rintf(v.y * rinv), -7, 7);
            q.z = (char)clampi((int)rintf(v.z * rinv), -7, 7);
            q.w = (char)clampi((int)rintf(v.w * rinv), -7, 7);
            o4[i] = q;
        }
    } else if (bx < 2208) {
        float s = g_maxabs[3] / 7.0f;
        int i = (bx - 2048) * 256 + tid;
        if (i < 10 * 4096)
            g_qwl2[i] = (int8_t)clampi((int)rintf(wl2[i] / s), -7, 7);
    } else if (bx < 2280) {
        float s = g_maxabs[1] / 7.0f;
        int i = (bx - 2208) * 256 + tid;
        if (i < 64 * 9 * 32) {
            int oc = i / 288, r = i % 288;
            int pos = r >> 5, ic = r & 31;
            float v = w2[(oc * 32 + ic) * 9 + pos];
            g_qw2[i] = (int8_t)clampi((int)rintf(v / s), -7, 7);
        }
    } else {
        float s = g_maxabs[0] / 7.0f;
        int i = (bx - 2280) * 256 + tid;
        if (i < 32 * 9)
            g_qw1[i] = (int8_t)clampi((int)rintf(w1[i] / s), -7, 7);
    }
}

// ---------------- fused conv1+pool+fq  ->  conv2(IMMA)+pool+fq ----------------
// conv1: 169 threads, one pool pixel each (4x4 receptive field in regs), dp4a.
// Pool-before-quantize (monotone map) + reciprocal multiplies (scales are 2^k).
#define A1S 48
#define WS2 304
__global__ __launch_bounds__(256) void conv12_k(const float* __restrict__ s_in_p,
                                                const float* __restrict__ s_a1_p,
                                                const float* __restrict__ s_a2_p) {
    __shared__ __align__(16) int8_t S[35072];
    int8_t* sw2 = S;                             // 64*304 = 19456
    int8_t* a1s = S + 19456;                     // act1 tile (stride 48), 8576
    int8_t* sx  = S + 28032;                     // 784
    uint32_t* swp = (uint32_t*)(S + 28832);      // packed conv1 weights, 96 u32
    int b = blockIdx.x, tid = threadIdx.x;
    int lane = tid & 31, wid = tid >> 5;

    for (int idx = tid; idx < 1152; idx += 256) {
        int row = idx / 18, seg = idx % 18;
        CPA16(smem_u32(sw2 + row * WS2 + seg * 16),
              (const char*)g_qw2 + row * 288 + seg * 16);
    }
    CPC();
    {
        const int* gx = (const int*)(g_qx + b * 784);
        int* sxi = (int*)sx;
        for (int i = tid; i < 196; i += 256) sxi[i] = gx[i];
        if (tid < 96) {  // pack w1[oc][ky][0..2] -> u32 with zero 4th byte
            int oc = tid / 3, ky = tid - oc * 3;
            const uint8_t* wp = (const uint8_t*)g_qw1 + oc * 9 + ky * 3;
            swp[tid] = (uint32_t)wp[0] | ((uint32_t)wp[1] << 8)
                     | ((uint32_t)wp[2] << 16);
        }
    }
    __syncthreads();

    float s_in = *s_in_p, s_a1 = *s_a1_p, s_a2 = *s_a2_p;
    float inv_in = 1.0f / s_in, inv_a1 = 1.0f / s_a1, inv_a2 = 1.0f / s_a2;
    float mul1 = s_in * (g_maxabs[0] / 7.0f);

    if (tid < 169) {
        int py = tid / 13, px = tid - py * 13;
        int c0 = 2 * px;
        uint32_t V[4];
        #pragma unroll
        for (int r = 0; r < 4; r++) {
            int boff = (2 * py + r) * 28 + c0;
            int b4 = boff & ~3;
            uint32_t lo = *(const uint32_t*)(sx + b4);
            if (boff & 2) {
                uint32_t hi = *(const uint32_t*)(sx + b4 + 4);
                V[r] = __funnelshift_r(lo, hi, 16);
            } else {
                V[r] = lo;
            }
        }
        uint32_t Q[4][2];
        #pragma unroll
        for (int r = 0; r < 4; r++) {
            Q[r][0] = V[r] & 0x00FFFFFFu;
            Q[r][1] = (V[r] >> 8) & 0x00FFFFFFu;
        }
        int8_t* arow = a1s + tid * A1S;
        #pragma unroll
        for (int g = 0; g < 8; g++) {
            uint32_t pk = 0;
            #pragma unroll
            for (int j = 0; j < 4; j++) {
                int oc = g * 4 + j;
                uint32_t w0 = swp[oc * 3 + 0], w1 = swp[oc * 3 + 1],
                         w2 = swp[oc * 3 + 2];
                int a00 = dp4(Q[0][0], w0, dp4(Q[1][0], w1, dp4(Q[2][0], w2, 0)));
                int a01 = dp4(Q[0][1], w0, dp4(Q[1][1], w1, dp4(Q[2][1], w2, 0)));
                int a10 = dp4(Q[1][0], w0, dp4(Q[2][0], w1, dp4(Q[3][0], w2, 0)));
                int a11 = dp4(Q[1][1], w0, dp4(Q[2][1], w1, dp4(Q[3][1], w2, 0)));
                int m = max(max(a00, a01), max(a10, a11));
                float v = (float)m * mul1;
                int q = clampi((int)rintf(v * inv_a1), 0, 15);
                float v2 = (float)q * s_a1;
                int q2 = clampi((int)rintf(v2 * inv_in), -8, 7);
                pk |= ((uint32_t)q2 & 0xFFu) << (j * 8);
            }
            *(uint32_t*)(arow + g * 4) = pk;
        }
    }
    CPW0();
    __syncthreads();

    // conv2 IMMA: A[128 conv-pix][288] gathered from a1s, B = sw2 [64 oc][288]
    int wm = wid >> 1, wn = wid & 1;
    int c[2][4][4];
    #pragma unroll
    for (int h = 0; h < 2; h++)
        #pragma unroll
        for (int nt = 0; nt < 4; nt++)
            #pragma unroll
            for (int e = 0; e < 4; e++) c[h][nt][e] = 0;

    uint32_t bbase = smem_u32(sw2)
                   + (wn * 32 + (lane & 7) + ((lane >> 4) << 3)) * WS2
                   + (((lane >> 3) & 1) << 4);
    uint32_t abase_h[2];
    {
        int khalf = lane >> 4;
        #pragma unroll
        for (int h = 0; h < 2; h++) {
            int p = h * 64 + wm * 16 + (lane & 15);
            int cy = p / 11, cx = p % 11;
            abase_h[h] = smem_u32(a1s) + (cy * 13 + cx) * A1S + khalf * 16;
        }
    }

    #pragma unroll
    for (int h = 0; h < 2; h++) {
        #pragma unroll
        for (int ks = 0; ks < 9; ks++) {
            int ky = ks / 3, kx = ks % 3;
            uint32_t a[4];
            ldsm4(a[0], a[1], a[2], a[3], abase_h[h] + (ky * 13 + kx) * A1S);
            uint32_t bb[4][2];
            #pragma unroll
            for (int j = 0; j < 2; j++) {
                uint32_t r0, r1, r2, r3;
                ldsm4(r0, r1, r2, r3, bbase + j * 16 * WS2 + ks * 32);
                bb[2 * j][0] = r0;     bb[2 * j][1] = r1;
                bb[2 * j + 1][0] = r2; bb[2 * j + 1][1] = r3;
            }
            #pragma unroll
            for (int nt = 0; nt < 4; nt++)
                imma16832(c[h][nt], a, bb[nt]);
        }
    }
    __syncthreads();   // done reading sw2/a1s -> reuse S as C

    int* Cs = (int*)S;  // [128 pix][68] int
    #pragma unroll
    for (int h = 0; h < 2; h++) {
        int row = h * 64 + wm * 16 + (lane >> 2);
        #pragma unroll
        for (int nt = 0; nt < 4; nt++) {
            int col = wn * 32 + nt * 8 + ((lane & 3) << 1);
            int2 v0 = make_int2(c[h][nt][0], c[h][nt][1]);
            int2 v1 = make_int2(c[h][nt][2], c[h][nt][3]);
            *(int2*)(Cs + row * 68 + col) = v0;
            *(int2*)(Cs + (row + 8) * 68 + col) = v1;
        }
    }
    __syncthreads();

    float mul2 = s_in * (g_maxabs[1] / 7.0f);
    for (int o = tid; o < 1600; o += 256) {
        int oc = o / 25, p = o - oc * 25;
        int py = p / 5, px = p - py * 5;
        int cp0 = (2 * py) * 11 + 2 * px;
        int m = Cs[cp0 * 68 + oc];
        m = max(m, Cs[(cp0 + 1) * 68 + oc]);
        m = max(m, Cs[(cp0 + 11) * 68 + oc]);
        m = max(m, Cs[(cp0 + 12) * 68 + oc]);
        float v = (float)m * mul2;
        int q = clampi((int)rintf(v * inv_a2), 0, 15);
        float v2 = (float)q * s_a2;
        int q2 = clampi((int)rintf(v2 * inv_in), -8, 7);
        g_act2[b * 1600 + o] = (int8_t)q2;
    }
}

// ---------------- fc1: s8 IMMA GEMM, 64x64 tiles for wave balance ----------------
// Grid (64, 16) = 1024 CTAs, 128 threads (4 warps 2x2), warp tile 32x32, BK=64.
__global__ __launch_bounds__(128) void fc1_imma_k(const float* __restrict__ s_in_p,
                                                  const float* __restrict__ s_a3_p) {
    __shared__ __align__(16) int8_t sA[2][64 * 80];
    __shared__ __align__(16) int8_t sB[2][64 * 80];
    const int BUFB = 64 * 80;

    int tid = threadIdx.x, lane = tid & 31, wid = tid >> 5;
    int wm = wid >> 1, wn = wid & 1;
    int bm = blockIdx.y, bn = blockIdx.x;

    int lrow = tid >> 1, lseg2 = (tid & 1) << 1;
    const char* gA0 = (const char*)g_act2 + (size_t)(bm * 64 + lrow) * 1600 + lseg2 * 16;
    const char* gB0 = (const char*)g_qwl1 + (size_t)(bn * 64 + lrow) * 1600 + lseg2 * 16;
    uint32_t smA0 = smem_u32(&sA[0][0]) + lrow * 80 + lseg2 * 16;
    uint32_t smB0 = smem_u32(&sB[0][0]) + lrow * 80 + lseg2 * 16;

    int c[2][4][4];
    #pragma unroll
    for (int i = 0; i < 2; i++)
        #pragma unroll
        for (int j = 0; j < 4; j++)
            #pragma unroll
            for (int e = 0; e < 4; e++) c[i][j][e] = 0;

    CPA16(smA0, gA0);
    CPA16(smA0 + 16, gA0 + 16);
    CPA16(smB0, gB0);
    CPA16(smB0 + 16, gB0 + 16);
    CPC(); CPW0();
    __syncthreads();

    uint32_t saL = smem_u32(&sA[0][0]) + (wm * 32 + (lane & 15)) * 80 + ((lane >> 4) << 4);
    uint32_t sbL = smem_u32(&sB[0][0])
                 + (wn * 32 + (lane & 7) + ((lane >> 4) << 3)) * 80
                 + (((lane >> 3) & 1) << 4);

    int buf = 0;
    for (int kt = 0; kt < 25; kt++) {
        if (kt < 24) {
            int nb = buf ^ 1;
            const char* ga = gA0 + (kt + 1) * 64;
            const char* gb = gB0 + (kt + 1) * 64;
            uint32_t da = smA0 + nb * BUFB, db = smB0 + nb * BUFB;
            CPA16(da, ga);
            CPA16(da + 16, ga + 16);
            CPA16(db, gb);
            CPA16(db + 16, gb + 16);
            CPC();
        }
        uint32_t sa = saL + buf * BUFB;
        uint32_t sb = sbL + buf * BUFB;
        #pragma unroll
        for (int ks = 0; ks < 2; ks++) {
            uint32_t a[2][4], bb[4][2];
            #pragma unroll
            for (int mt = 0; mt < 2; mt++)
                ldsm4(a[mt][0], a[mt][1], a[mt][2], a[mt][3],
                      sa + mt * 16 * 80 + ks * 32);
            #pragma unroll
            for (int j = 0; j < 2; j++) {
                uint32_t r0, r1, r2, r3;
                ldsm4(r0, r1, r2, r3, sb + j * 16 * 80 + ks * 32);
                bb[2 * j][0] = r0;     bb[2 * j][1] = r1;
                bb[2 * j + 1][0] = r2; bb[2 * j + 1][1] = r3;
            }
            #pragma unroll
            for (int mt = 0; mt < 2; mt++)
                #pragma unroll
                for (int nt = 0; nt < 4; nt++)
                    imma16832(c[mt][nt], a[mt], bb[nt]);
        }
        if (kt < 24) {
            CPW0();
            __syncthreads();
            buf ^= 1;
        }
    }

    float s_in = *s_in_p, s_a3 = *s_a3_p;
    float mul = s_in * (g_maxabs[2] / 7.0f);
    float isa3 = 1.0f / s_a3;  // power of two -> exact
    int r0 = bm * 64 + wm * 32 + (lane >> 2);
    int c0 = bn * 64 + wn * 32 + ((lane & 3) << 1);
    #pragma unroll
    for (int mt = 0; mt < 2; mt++) {
        #pragma unroll
        for (int nt = 0; nt < 4; nt++) {
            int rr = r0 + mt * 16, cc = c0 + nt * 8;
            int* cf = c[mt][nt];
            uchar2 lo, hi;
            lo.x = (uint8_t)clampi((int)rintf((float)cf[0] * mul * isa3), 0, 15);
            lo.y = (uint8_t)clampi((int)rintf((float)cf[1] * mul * isa3), 0, 15);
            hi.x = (uint8_t)clampi((int)rintf((float)cf[2] * mul * isa3), 0, 15);
            hi.y = (uint8_t)clampi((int)rintf((float)cf[3] * mul * isa3), 0, 15);
            *(uchar2*)(g_act3 + rr * 4096 + cc) = lo;
            *(uchar2*)(g_act3 + (rr + 8) * 4096 + cc) = hi;
        }
    }
}

// ---------------- fc2: [1024,4096] x [10,4096]^T -> out (+ scale reset tail) ----
__global__ void fc2_k(const float* __restrict__ s_a3_p, float* __restrict__ out) {
    int b = blockIdx.x;
    int wj = threadIdx.x >> 5, lane = threadIdx.x & 31;
    const int* ar = (const int*)(g_act3 + b * 4096);
    const int* wr = (const int*)(g_qwl2 + wj * 4096);
    int acc = 0;
    for (int t = lane; t < 1024; t += 32)
        acc = __dp4a(ar[t], wr[t], acc);
    #pragma unroll
    for (int o = 16; o; o >>= 1) acc += __shfl_xor_sync(0xffffffffu, acc, o);
    if (lane == 0)
        out[b * 10 + wj] = (float)acc * (*s_a3_p) * (g_maxabs[3] / 7.0f);

    // last-finishing block resets scales for the next replay (deterministic)
    __syncthreads();
    if (threadIdx.x == 0) {
        __threadfence();
        if (atomicAdd(&g_cnt2, 1) == (int)gridDim.x - 1) {
            g_maxabs[0] = 0.0f; g_maxabs[1] = 0.0f;
            g_maxabs[2] = 0.0f; g_maxabs[3] = 0.0f;
            g_cnt2 = 0;
            __threadfence();
        }
    }
}

// ---------------- launcher ----------------
extern "C" void kernel_launch(void* const* d_in, const int* in_sizes, int n_in,
                              void* d_out, int out_size) {
    const float* x    = (const float*)d_in[0];
    const float* w1   = (const float*)d_in[1];
    const float* w2   = (const float*)d_in[2];
    const float* wl1  = (const float*)d_in[3];
    const float* wl2  = (const float*)d_in[4];
    const float* s_in = (const float*)d_in[5];
    const float* s_a1 = (const float*)d_in[6];
    const float* s_a2 = (const float*)d_in[7];
    const float* s_a3 = (const float*)d_in[8];
    float* out = (float*)d_out;

    prep1_k<<<1475, 256>>>(w1, w2, wl1, wl2, x, s_in);   // maxabs + quant_x
    quant_w_k<<<2282, 256>>>(w1, w2, wl1, wl2);
    conv12_k<<<1024, 256>>>(s_in, s_a1, s_a2);
    fc1_imma_k<<<dim3(64, 16), 128>>>(s_in, s_a3);       // 4th launch -> ncu capture
    fc2_k<<<1024, 320>>>(s_a3, out);
}